// round 10
// baseline (speedup 1.0000x reference)
#include <cuda_runtime.h>

#define NNODES 50000
#define NEDGES 800000
#define FDIM   64
#define NCHUNK 196        // ceil(NNODES/256)

// ---------------- scratch (static device globals; no runtime alloc) ----------------
__device__ __align__(16) float g_x[NNODES * FDIM];     // post-relu features
__device__ __align__(16) float g_xr[NNODES * FDIM];    // x @ W_rel.T  (gathered over edges)
__device__ __align__(16) float g_root[NNODES * FDIM];  // x @ W_root.T (agg init)
__device__ float4 g_xr4[NNODES];                       // iter-3 sparse columns (rel)
__device__ float4 g_root4[NNODES];                     // iter-3 sparse columns (root)
__device__ __align__(16) float2 g_Wt2[FDIM * 128];     // tf32-split W.T: [k][o] -> (hi,lo)
__device__ int g_rowptr[NNODES + 1];
__device__ int g_cursor[NNODES];
__device__ int g_ssrc[NEDGES];
__device__ int g_partial[256];
__device__ int g_is64;

__device__ __forceinline__ unsigned f2tf32(float f) {
    unsigned u;
    asm("cvt.rna.tf32.f32 %0, %1;" : "=r"(u) : "f"(f));
    return u;
}

// ---------------- dtype detection + one-time W split (fused; keeps launch slots) -------
__global__ void detect_prep_kernel(const void* ei_raw,
                                   const float* __restrict__ Wrel,
                                   const float* __restrict__ Wroot) {
    __shared__ int any_nonzero;
    int t = threadIdx.x;
    if (t == 0) any_nonzero = 0;
    __syncthreads();
    const int* w = (const int*)ei_raw;
    if (w[2 * t + 1] != 0) atomicOr(&any_nonzero, 1);

    // W.T split into (hi, lo) tf32 pairs: g_Wt2[k*128 + o] = split(W[o][k])
    #pragma unroll
    for (int i = t; i < FDIM * 128; i += 1024) {
        int k = i >> 7, o = i & 127;
        float val = (o < 64) ? Wrel[o * FDIM + k] : Wroot[(o - 64) * FDIM + k];
        float hi = __uint_as_float(f2tf32(val));
        float lo = __uint_as_float(f2tf32(val - hi));
        g_Wt2[i] = make_float2(hi, lo);
    }
    __syncthreads();
    if (t == 0) g_is64 = any_nonzero ? 0 : 1;
}

__device__ __forceinline__ int load_idx(const void* ei_raw, int pos, int is64) {
    if (is64) return (int)((const long long*)ei_raw)[pos];
    return ((const int*)ei_raw)[pos];
}

// ---------------- CSR build (by dst) ----------------
__global__ void zero_counts_kernel() {
    int i = blockIdx.x * blockDim.x + threadIdx.x;
    if (i < NNODES) g_cursor[i] = 0;
}

__global__ void hist_kernel(const void* __restrict__ ei_raw) {
    int e = blockIdx.x * blockDim.x + threadIdx.x;
    if (e < NEDGES) {
        int d = load_idx(ei_raw, NEDGES + e, g_is64);
        if ((unsigned)d < (unsigned)NNODES) atomicAdd(&g_cursor[d], 1);
    }
}

__global__ void chunk_reduce_kernel() {
    int i = blockIdx.x * 256 + threadIdx.x;
    int v = (i < NNODES) ? g_cursor[i] : 0;
    #pragma unroll
    for (int off = 16; off; off >>= 1) v += __shfl_down_sync(0xffffffffu, v, off);
    __shared__ int ws[8];
    if ((threadIdx.x & 31) == 0) ws[threadIdx.x >> 5] = v;
    __syncthreads();
    if (threadIdx.x < 8) {
        int s = ws[threadIdx.x];
        #pragma unroll
        for (int off = 4; off; off >>= 1) s += __shfl_down_sync(0xffu, s, off);
        if (threadIdx.x == 0) g_partial[blockIdx.x] = s;
    }
}

__global__ void partial_scan_kernel() {
    __shared__ int ps[256];
    int t = threadIdx.x;
    int v = (t < NCHUNK) ? g_partial[t] : 0;
    ps[t] = v;
    __syncthreads();
    #pragma unroll
    for (int off = 1; off < 256; off <<= 1) {
        int u = (t >= off) ? ps[t - off] : 0;
        __syncthreads();
        ps[t] += u;
        __syncthreads();
    }
    if (t < NCHUNK) g_partial[t] = ps[t] - v;
    if (t == 255) g_rowptr[NNODES] = ps[255];
}

__global__ void chunk_scan_kernel() {
    __shared__ int ps[256];
    int t = threadIdx.x;
    int i = blockIdx.x * 256 + t;
    int v = (i < NNODES) ? g_cursor[i] : 0;
    ps[t] = v;
    __syncthreads();
    #pragma unroll
    for (int off = 1; off < 256; off <<= 1) {
        int u = (t >= off) ? ps[t - off] : 0;
        __syncthreads();
        ps[t] += u;
        __syncthreads();
    }
    int excl = ps[t] - v + g_partial[blockIdx.x];
    if (i < NNODES) { g_rowptr[i] = excl; g_cursor[i] = excl; }
}

__global__ void scatter_kernel(const void* __restrict__ ei_raw) {
    int e = blockIdx.x * blockDim.x + threadIdx.x;
    if (e < NEDGES) {
        int is64 = g_is64;
        int d = load_idx(ei_raw, NEDGES + e, is64);
        int s = load_idx(ei_raw, e, is64);
        if ((unsigned)d < (unsigned)NNODES && (unsigned)s < (unsigned)NNODES) {
            int p = atomicAdd(&g_cursor[d], 1);
            g_ssrc[p] = s;
        }
    }
}

// ---------------- split-tf32 tensor GEMM: [xr | root] = x @ [W_rel | W_root].T ---------
// Block: 64 nodes x 128 outputs x K=64. 8 warps (4M x 2N); warp tile 16x64.
// Only X staged in (static) smem; B fragments read via __ldg from L2-hot g_Wt2.
#define GM       64
#define XK_STR   68            // float2 stride: phase banks (8r+2c)%32 conflict-free

__global__ void __launch_bounds__(256)
mma_gemm_kernel(const float* __restrict__ xext, int first)
{
    __shared__ float2 Xs2[GM * XK_STR];   // 34816 B static

    const float* xin = first ? xext : g_x;
    int tid = threadIdx.x;
    int nbase = blockIdx.x * GM;

    // ---- X tile: 64 nodes x 64 k, split into (hi, lo) ----
    #pragma unroll
    for (int it = 0; it < 4; ++it) {
        int idx = tid + it * 256;          // 0..1023 float4 chunks
        int n   = idx >> 4;
        int kc  = idx & 15;
        int gn  = nbase + n;
        float4 v = make_float4(0.f, 0.f, 0.f, 0.f);
        if (gn < NNODES) v = *(const float4*)&xin[gn * FDIM + kc * 4];
        float vv[4] = {v.x, v.y, v.z, v.w};
        #pragma unroll
        for (int u = 0; u < 4; ++u) {
            float hi = __uint_as_float(f2tf32(vv[u]));
            float lo = __uint_as_float(f2tf32(vv[u] - hi));
            Xs2[n * XK_STR + kc * 4 + u] = make_float2(hi, lo);
        }
    }
    __syncthreads();

    int warp = tid >> 5;
    int lane = tid & 31;
    int m0    = (warp >> 1) * 16;
    int nhalf = warp & 1;              // 0 -> g_xr, 1 -> g_root
    int n0    = nhalf * 64;

    int ar = m0 + (lane >> 2);
    int ac = lane & 3;
    int bq = lane >> 2;
    int bc = lane & 3;

    float c[8][4];
    #pragma unroll
    for (int j = 0; j < 8; ++j)
        #pragma unroll
        for (int q = 0; q < 4; ++q) c[j][q] = 0.f;

    #pragma unroll
    for (int ks = 0; ks < 8; ++ks) {
        int k0 = ks * 8;
        float2 A0 = Xs2[ar * XK_STR + k0 + ac];
        float2 A1 = Xs2[(ar + 8) * XK_STR + k0 + ac];
        float2 A2 = Xs2[ar * XK_STR + k0 + ac + 4];
        float2 A3 = Xs2[(ar + 8) * XK_STR + k0 + ac + 4];
        unsigned ah0 = __float_as_uint(A0.x), ah1 = __float_as_uint(A1.x);
        unsigned ah2 = __float_as_uint(A2.x), ah3 = __float_as_uint(A3.x);
        unsigned al0 = __float_as_uint(A0.y), al1 = __float_as_uint(A1.y);
        unsigned al2 = __float_as_uint(A2.y), al3 = __float_as_uint(A3.y);
        #pragma unroll
        for (int j = 0; j < 8; ++j) {
            int n = n0 + j * 8 + bq;
            float2 B0 = __ldg(&g_Wt2[(k0 + bc) * 128 + n]);
            float2 B1 = __ldg(&g_Wt2[(k0 + bc + 4) * 128 + n]);
            unsigned bh0 = __float_as_uint(B0.x), bh1 = __float_as_uint(B1.x);
            unsigned bl0 = __float_as_uint(B0.y), bl1 = __float_as_uint(B1.y);
            asm("mma.sync.aligned.m16n8k8.row.col.f32.tf32.tf32.f32 "
                "{%0,%1,%2,%3}, {%4,%5,%6,%7}, {%8,%9}, {%0,%1,%2,%3};"
                : "+f"(c[j][0]), "+f"(c[j][1]), "+f"(c[j][2]), "+f"(c[j][3])
                : "r"(ah0), "r"(ah1), "r"(ah2), "r"(ah3), "r"(bh0), "r"(bh1));
            asm("mma.sync.aligned.m16n8k8.row.col.f32.tf32.tf32.f32 "
                "{%0,%1,%2,%3}, {%4,%5,%6,%7}, {%8,%9}, {%0,%1,%2,%3};"
                : "+f"(c[j][0]), "+f"(c[j][1]), "+f"(c[j][2]), "+f"(c[j][3])
                : "r"(ah0), "r"(ah1), "r"(ah2), "r"(ah3), "r"(bl0), "r"(bl1));
            asm("mma.sync.aligned.m16n8k8.row.col.f32.tf32.tf32.f32 "
                "{%0,%1,%2,%3}, {%4,%5,%6,%7}, {%8,%9}, {%0,%1,%2,%3};"
                : "+f"(c[j][0]), "+f"(c[j][1]), "+f"(c[j][2]), "+f"(c[j][3])
                : "r"(al0), "r"(al1), "r"(al2), "r"(al3), "r"(bh0), "r"(bh1));
        }
    }

    float* dst = nhalf ? g_root : g_xr;
    int nodeA = nbase + m0 + (lane >> 2);
    int nodeB = nodeA + 8;
    #pragma unroll
    for (int j = 0; j < 8; ++j) {
        int col = j * 8 + 2 * (lane & 3);
        if (nodeA < NNODES)
            *(float2*)&dst[nodeA * FDIM + col] = make_float2(c[j][0], c[j][1]);
        if (nodeB < NNODES)
            *(float2*)&dst[nodeB * FDIM + col] = make_float2(c[j][2], c[j][3]);
    }
}

// ---------------- full aggregation (iters 1,2): warp per node, float2 per lane ---------
__global__ void agg_kernel()
{
    int gw   = (blockIdx.x * blockDim.x + threadIdx.x) >> 5;
    int lane = threadIdx.x & 31;
    if (gw >= NNODES) return;

    const float2* __restrict__ xr2 = (const float2*)g_xr;
    float2 acc = *(const float2*)&g_root[gw * FDIM + lane * 2];

    int e   = g_rowptr[gw];
    int end = g_rowptr[gw + 1];
    for (; e + 8 <= end; e += 8) {
        int s[8];
        #pragma unroll
        for (int q = 0; q < 8; ++q) s[q] = g_ssrc[e + q];
        float2 a[8];
        #pragma unroll
        for (int q = 0; q < 8; ++q) a[q] = xr2[s[q] * 32 + lane];
        #pragma unroll
        for (int q = 0; q < 8; ++q) { acc.x += a[q].x; acc.y += a[q].y; }
    }
    for (; e < end; ++e) {
        int sv = g_ssrc[e];
        float2 a = xr2[sv * 32 + lane];
        acc.x += a.x;
        acc.y += a.y;
    }
    acc.x = fmaxf(acc.x, 0.f);
    acc.y = fmaxf(acc.y, 0.f);
    *(float2*)&g_x[gw * FDIM + lane * 2] = acc;
}

// ---------------- iter-3 sparse GEMM: only readout features {15,31,47,63} --------------
__constant__ int c_pos[4] = {15, 31, 47, 63};

__global__ void gemm4_kernel(const float* __restrict__ Wrel,
                             const float* __restrict__ Wroot)
{
    __shared__ float4 Wsel[8][16];
    int tid = threadIdx.x;
    if (tid < 128) {
        int r = tid >> 4, kc = tid & 15;
        const float* src = (r < 4) ? &Wrel[c_pos[r] * FDIM] : &Wroot[c_pos[r - 4] * FDIM];
        Wsel[r][kc] = *(const float4*)&src[kc * 4];
    }
    __syncthreads();

    int n = blockIdx.x * blockDim.x + tid;
    if (n >= NNODES) return;

    float acc[8];
    #pragma unroll
    for (int r = 0; r < 8; ++r) acc[r] = 0.f;

    const float4* xrow = (const float4*)&g_x[n * FDIM];
    #pragma unroll
    for (int kc = 0; kc < 16; ++kc) {
        float4 xv = xrow[kc];
        #pragma unroll
        for (int r = 0; r < 8; ++r) {
            float4 w = Wsel[r][kc];
            acc[r] += xv.x * w.x + xv.y * w.y + xv.z * w.z + xv.w * w.w;
        }
    }
    g_xr4[n]   = make_float4(acc[0], acc[1], acc[2], acc[3]);
    g_root4[n] = make_float4(acc[4], acc[5], acc[6], acc[7]);
}

// ---------------- iter-3 aggregation + readout: thread per node ----------
__global__ void agg4_kernel(const float* __restrict__ evec, float* __restrict__ out)
{
    int n = blockIdx.x * blockDim.x + threadIdx.x;
    if (n >= NNODES) return;

    float4 acc = g_root4[n];
    int e   = g_rowptr[n];
    int end = g_rowptr[n + 1];
    for (; e + 4 <= end; e += 4) {
        int s0 = g_ssrc[e],     s1 = g_ssrc[e + 1];
        int s2 = g_ssrc[e + 2], s3 = g_ssrc[e + 3];
        float4 a0 = g_xr4[s0], a1 = g_xr4[s1];
        float4 a2 = g_xr4[s2], a3 = g_xr4[s3];
        acc.x += (a0.x + a1.x) + (a2.x + a3.x);
        acc.y += (a0.y + a1.y) + (a2.y + a3.y);
        acc.z += (a0.z + a1.z) + (a2.z + a3.z);
        acc.w += (a0.w + a1.w) + (a2.w + a3.w);
    }
    for (; e < end; ++e) {
        float4 a = g_xr4[g_ssrc[e]];
        acc.x += a.x; acc.y += a.y; acc.z += a.z; acc.w += a.w;
    }
    out[n] = fmaxf(acc.x, 0.f) * evec[15] + fmaxf(acc.y, 0.f) * evec[31]
           + fmaxf(acc.z, 0.f) * evec[47] + fmaxf(acc.w, 0.f) * evec[63];
}

// ---------------- launch ----------------
extern "C" void kernel_launch(void* const* d_in, const int* in_sizes, int n_in,
                              void* d_out, int out_size) {
    const float* x = 0; const void* ei = 0;
    const float* Wrel = 0; const float* Wroot = 0; const float* evec = 0;
    for (int i = 0; i < n_in; ++i) {
        int sz = in_sizes[i];
        if (sz == NNODES * FDIM)      x = (const float*)d_in[i];
        else if (sz == 2 * NEDGES)    ei = d_in[i];
        else if (sz == FDIM * FDIM) { if (!Wrel) Wrel = (const float*)d_in[i];
                                      else       Wroot = (const float*)d_in[i]; }
        else if (sz == FDIM)          evec = (const float*)d_in[i];
    }
    float* out = (float*)d_out;

    const int GB = (NNODES + GM - 1) / GM;     // 782
    const int AB = (NNODES + 7) / 8;           // 6250
    const int TB = (NNODES + 255) / 256;       // 196

    detect_prep_kernel<<<1, 1024>>>(ei, Wrel, Wroot);
    zero_counts_kernel<<<TB, 256>>>();
    hist_kernel<<<(NEDGES + 255) / 256, 256>>>(ei);

    mma_gemm_kernel<<<GB, 256>>>(x, 1);                   // iter-1 (profiled slot)

    chunk_reduce_kernel<<<NCHUNK, 256>>>();
    partial_scan_kernel<<<1, 256>>>();
    chunk_scan_kernel<<<NCHUNK, 256>>>();
    scatter_kernel<<<(NEDGES + 255) / 256, 256>>>(ei);

    agg_kernel<<<AB, 256>>>();                            // iter 1
    mma_gemm_kernel<<<GB, 256>>>(x, 0);                   // iter 2
    agg_kernel<<<AB, 256>>>();
    gemm4_kernel<<<TB, 256>>>(Wrel, Wroot);               // iter 3 (sparse)
    agg4_kernel<<<TB, 256>>>(evec, out);
}

// round 11
// speedup vs baseline: 1.2284x; 1.2284x over previous
#include <cuda_runtime.h>

#define NNODES 50000
#define NEDGES 800000
#define FDIM   64
#define NCHUNK 196        // ceil(NNODES/256)

// ---------------- scratch (static device globals; no runtime alloc) ----------------
__device__ __align__(16) float g_x[NNODES * FDIM];     // post-relu features
__device__ __align__(16) float g_xr[NNODES * FDIM];    // x @ W_rel.T  (gathered over edges)
__device__ __align__(16) float g_root[NNODES * FDIM];  // x @ W_root.T (agg init)
__device__ float4 g_xr4[NNODES];                       // iter-3 sparse columns (rel)
__device__ float4 g_root4[NNODES];                     // iter-3 sparse columns (root)
__device__ __align__(16) float4 g_Wp[4096];            // packed tf32-split W (64KB)
__device__ int g_rowptr[NNODES + 1];
__device__ int g_cursor[NNODES];
__device__ int g_ssrc[NEDGES];
__device__ int g_partial[256];
__device__ int g_is64;

__device__ __forceinline__ unsigned f2tf32(float f) {
    unsigned u;
    asm("cvt.rna.tf32.f32 %0, %1;" : "=r"(u) : "f"(f));
    return u;
}

// ---------------- dtype detection + one-time packed W split ----------------
// g_Wp[ks*512 + n*4 + bc] = {hi(W[n][k0+bc]), hi(W[n][k0+bc+4]),
//                            lo(W[n][k0+bc]), lo(W[n][k0+bc+4])}, k0 = ks*8.
// n < 64 -> W_rel row n ; n >= 64 -> W_root row n-64.
__global__ void detect_prep_kernel(const void* ei_raw,
                                   const float* __restrict__ Wrel,
                                   const float* __restrict__ Wroot) {
    __shared__ int any_nonzero;
    int t = threadIdx.x;
    if (t == 0) any_nonzero = 0;
    __syncthreads();
    const int* w = (const int*)ei_raw;
    if (w[2 * t + 1] != 0) atomicOr(&any_nonzero, 1);

    for (int i = t; i < 4096; i += 1024) {
        int ks = i >> 9, n = (i >> 2) & 127, bc = i & 3;
        int k1 = ks * 8 + bc, k2 = k1 + 4;
        const float* src = (n < 64) ? &Wrel[n * FDIM] : &Wroot[(n - 64) * FDIM];
        float v1 = src[k1], v2 = src[k2];
        float h1 = __uint_as_float(f2tf32(v1));
        float h2 = __uint_as_float(f2tf32(v2));
        g_Wp[i] = make_float4(h1, h2, v1 - h1 == 0.f ? 0.f : __uint_as_float(f2tf32(v1 - h1)),
                              v2 - h2 == 0.f ? 0.f : __uint_as_float(f2tf32(v2 - h2)));
    }
    __syncthreads();
    if (t == 0) g_is64 = any_nonzero ? 0 : 1;
}

__device__ __forceinline__ int load_idx(const void* ei_raw, int pos, int is64) {
    if (is64) return (int)((const long long*)ei_raw)[pos];
    return ((const int*)ei_raw)[pos];
}

// ---------------- CSR build (by dst) ----------------
__global__ void zero_counts_kernel() {
    int i = blockIdx.x * blockDim.x + threadIdx.x;
    if (i < NNODES) g_cursor[i] = 0;
}

__global__ void hist_kernel(const void* __restrict__ ei_raw) {
    int e = blockIdx.x * blockDim.x + threadIdx.x;
    if (e < NEDGES) {
        int d = load_idx(ei_raw, NEDGES + e, g_is64);
        if ((unsigned)d < (unsigned)NNODES) atomicAdd(&g_cursor[d], 1);
    }
}

__global__ void chunk_reduce_kernel() {
    int i = blockIdx.x * 256 + threadIdx.x;
    int v = (i < NNODES) ? g_cursor[i] : 0;
    #pragma unroll
    for (int off = 16; off; off >>= 1) v += __shfl_down_sync(0xffffffffu, v, off);
    __shared__ int ws[8];
    if ((threadIdx.x & 31) == 0) ws[threadIdx.x >> 5] = v;
    __syncthreads();
    if (threadIdx.x < 8) {
        int s = ws[threadIdx.x];
        #pragma unroll
        for (int off = 4; off; off >>= 1) s += __shfl_down_sync(0xffu, s, off);
        if (threadIdx.x == 0) g_partial[blockIdx.x] = s;
    }
}

__global__ void partial_scan_kernel() {
    __shared__ int ps[256];
    int t = threadIdx.x;
    int v = (t < NCHUNK) ? g_partial[t] : 0;
    ps[t] = v;
    __syncthreads();
    #pragma unroll
    for (int off = 1; off < 256; off <<= 1) {
        int u = (t >= off) ? ps[t - off] : 0;
        __syncthreads();
        ps[t] += u;
        __syncthreads();
    }
    if (t < NCHUNK) g_partial[t] = ps[t] - v;
    if (t == 255) g_rowptr[NNODES] = ps[255];
}

__global__ void chunk_scan_kernel() {
    __shared__ int ps[256];
    int t = threadIdx.x;
    int i = blockIdx.x * 256 + t;
    int v = (i < NNODES) ? g_cursor[i] : 0;
    ps[t] = v;
    __syncthreads();
    #pragma unroll
    for (int off = 1; off < 256; off <<= 1) {
        int u = (t >= off) ? ps[t - off] : 0;
        __syncthreads();
        ps[t] += u;
        __syncthreads();
    }
    int excl = ps[t] - v + g_partial[blockIdx.x];
    if (i < NNODES) { g_rowptr[i] = excl; g_cursor[i] = excl; }
}

__global__ void scatter_kernel(const void* __restrict__ ei_raw) {
    int e = blockIdx.x * blockDim.x + threadIdx.x;
    if (e < NEDGES) {
        int is64 = g_is64;
        int d = load_idx(ei_raw, NEDGES + e, is64);
        int s = load_idx(ei_raw, e, is64);
        if ((unsigned)d < (unsigned)NNODES && (unsigned)s < (unsigned)NNODES) {
            int p = atomicAdd(&g_cursor[d], 1);
            g_ssrc[p] = s;
        }
    }
}

// ---------------- split-tf32 tensor GEMM: [xr | root] = x @ [W_rel | W_root].T ---------
// Block 64 nodes x 128 outputs x K=64. 8 warps, warp tile 32M x 32N.
// A packed in smem (float4 {hi,hi+4,lo,lo+4}, node stride 36 float4 -> conflict-free).
// B packed in global g_Wp, one LDG.128 per thread per (ks,j) -> L1-resident.
#define GM 64

__global__ void __launch_bounds__(256)
mma_gemm_kernel(const float* __restrict__ xext, int first)
{
    __shared__ float4 Xa[GM * 36];     // 36864 B static

    const float* xin = first ? xext : g_x;
    int tid = threadIdx.x;
    int nbase = blockIdx.x * GM;

    // ---- prologue: split X tile into packed fragments ----
    // chunk kc (4 consecutive k): ks = kc>>1, h = kc&1; value u -> slot (ks*4+u), comp h (hi) / 2+h (lo)
    float* Xf = (float*)Xa;
    #pragma unroll
    for (int it = 0; it < 4; ++it) {
        int idx = tid + it * 256;          // 0..1023
        int n   = idx >> 4;
        int kc  = idx & 15;
        int gn  = nbase + n;
        float4 v = make_float4(0.f, 0.f, 0.f, 0.f);
        if (gn < NNODES) v = *(const float4*)&xin[gn * FDIM + kc * 4];
        int ks = kc >> 1, h = kc & 1;
        float vv[4] = {v.x, v.y, v.z, v.w};
        #pragma unroll
        for (int u = 0; u < 4; ++u) {
            float hi = __uint_as_float(f2tf32(vv[u]));
            float lo = __uint_as_float(f2tf32(vv[u] - hi));
            int base = (n * 36 + ks * 4 + u) * 4;
            Xf[base + h]     = hi;
            Xf[base + 2 + h] = lo;
        }
    }
    __syncthreads();

    int warp = tid >> 5;
    int lane = tid & 31;
    int m0 = (warp >> 2) * 32;         // 0 or 32
    int n0 = (warp & 3) * 32;          // 0,32,64,96
    int r  = lane >> 2;                // 0..7 (A row offset & B col offset)
    int ac = lane & 3;                 // A k-offset & B k-offset

    float c[2][4][4];
    #pragma unroll
    for (int t = 0; t < 2; ++t)
        #pragma unroll
        for (int j = 0; j < 4; ++j)
            #pragma unroll
            for (int q = 0; q < 4; ++q) c[t][j][q] = 0.f;

    int ra = m0 + r;
    #pragma unroll
    for (int ks = 0; ks < 8; ++ks) {
        float4 a0 = Xa[(ra)      * 36 + ks * 4 + ac];
        float4 a1 = Xa[(ra + 8)  * 36 + ks * 4 + ac];
        float4 a2 = Xa[(ra + 16) * 36 + ks * 4 + ac];
        float4 a3 = Xa[(ra + 24) * 36 + ks * 4 + ac];
        unsigned ahi[2][4], alo[2][4];
        ahi[0][0] = __float_as_uint(a0.x); ahi[0][1] = __float_as_uint(a1.x);
        ahi[0][2] = __float_as_uint(a0.y); ahi[0][3] = __float_as_uint(a1.y);
        alo[0][0] = __float_as_uint(a0.z); alo[0][1] = __float_as_uint(a1.z);
        alo[0][2] = __float_as_uint(a0.w); alo[0][3] = __float_as_uint(a1.w);
        ahi[1][0] = __float_as_uint(a2.x); ahi[1][1] = __float_as_uint(a3.x);
        ahi[1][2] = __float_as_uint(a2.y); ahi[1][3] = __float_as_uint(a3.y);
        alo[1][0] = __float_as_uint(a2.z); alo[1][1] = __float_as_uint(a3.z);
        alo[1][2] = __float_as_uint(a2.w); alo[1][3] = __float_as_uint(a3.w);
        #pragma unroll
        for (int j = 0; j < 4; ++j) {
            int n = n0 + j * 8 + r;
            float4 b = __ldg(&g_Wp[ks * 512 + n * 4 + ac]);
            unsigned bh0 = __float_as_uint(b.x), bh1 = __float_as_uint(b.y);
            unsigned bl0 = __float_as_uint(b.z), bl1 = __float_as_uint(b.w);
            #pragma unroll
            for (int t = 0; t < 2; ++t) {
                asm("mma.sync.aligned.m16n8k8.row.col.f32.tf32.tf32.f32 "
                    "{%0,%1,%2,%3}, {%4,%5,%6,%7}, {%8,%9}, {%0,%1,%2,%3};"
                    : "+f"(c[t][j][0]), "+f"(c[t][j][1]), "+f"(c[t][j][2]), "+f"(c[t][j][3])
                    : "r"(ahi[t][0]), "r"(ahi[t][1]), "r"(ahi[t][2]), "r"(ahi[t][3]),
                      "r"(bh0), "r"(bh1));
                asm("mma.sync.aligned.m16n8k8.row.col.f32.tf32.tf32.f32 "
                    "{%0,%1,%2,%3}, {%4,%5,%6,%7}, {%8,%9}, {%0,%1,%2,%3};"
                    : "+f"(c[t][j][0]), "+f"(c[t][j][1]), "+f"(c[t][j][2]), "+f"(c[t][j][3])
                    : "r"(ahi[t][0]), "r"(ahi[t][1]), "r"(ahi[t][2]), "r"(ahi[t][3]),
                      "r"(bl0), "r"(bl1));
                asm("mma.sync.aligned.m16n8k8.row.col.f32.tf32.tf32.f32 "
                    "{%0,%1,%2,%3}, {%4,%5,%6,%7}, {%8,%9}, {%0,%1,%2,%3};"
                    : "+f"(c[t][j][0]), "+f"(c[t][j][1]), "+f"(c[t][j][2]), "+f"(c[t][j][3])
                    : "r"(alo[t][0]), "r"(alo[t][1]), "r"(alo[t][2]), "r"(alo[t][3]),
                      "r"(bh0), "r"(bh1));
            }
        }
    }

    float* dst;
    int col0;
    if (n0 < 64) { dst = g_xr;   col0 = n0; }
    else         { dst = g_root; col0 = n0 - 64; }
    #pragma unroll
    for (int t = 0; t < 2; ++t) {
        int nodeA = nbase + m0 + 16 * t + r;
        int nodeB = nodeA + 8;
        #pragma unroll
        for (int j = 0; j < 4; ++j) {
            int col = col0 + j * 8 + 2 * ac;
            if (nodeA < NNODES)
                *(float2*)&dst[nodeA * FDIM + col] = make_float2(c[t][j][0], c[t][j][1]);
            if (nodeB < NNODES)
                *(float2*)&dst[nodeB * FDIM + col] = make_float2(c[t][j][2], c[t][j][3]);
        }
    }
}

// ---------------- full aggregation (iters 1,2): warp per node, float2 per lane ---------
__global__ void agg_kernel()
{
    int gw   = (blockIdx.x * blockDim.x + threadIdx.x) >> 5;
    int lane = threadIdx.x & 31;
    if (gw >= NNODES) return;

    const float2* __restrict__ xr2 = (const float2*)g_xr;
    float2 acc = *(const float2*)&g_root[gw * FDIM + lane * 2];

    int e   = g_rowptr[gw];
    int end = g_rowptr[gw + 1];
    for (; e + 8 <= end; e += 8) {
        int s[8];
        #pragma unroll
        for (int q = 0; q < 8; ++q) s[q] = g_ssrc[e + q];
        float2 a[8];
        #pragma unroll
        for (int q = 0; q < 8; ++q) a[q] = xr2[s[q] * 32 + lane];
        #pragma unroll
        for (int q = 0; q < 8; ++q) { acc.x += a[q].x; acc.y += a[q].y; }
    }
    for (; e < end; ++e) {
        int sv = g_ssrc[e];
        float2 a = xr2[sv * 32 + lane];
        acc.x += a.x;
        acc.y += a.y;
    }
    acc.x = fmaxf(acc.x, 0.f);
    acc.y = fmaxf(acc.y, 0.f);
    *(float2*)&g_x[gw * FDIM + lane * 2] = acc;
}

// ---------------- iter-3 sparse GEMM: only readout features {15,31,47,63} --------------
__constant__ int c_pos[4] = {15, 31, 47, 63};

__global__ void gemm4_kernel(const float* __restrict__ Wrel,
                             const float* __restrict__ Wroot)
{
    __shared__ float4 Wsel[8][16];
    int tid = threadIdx.x;
    if (tid < 128) {
        int r = tid >> 4, kc = tid & 15;
        const float* src = (r < 4) ? &Wrel[c_pos[r] * FDIM] : &Wroot[c_pos[r - 4] * FDIM];
        Wsel[r][kc] = *(const float4*)&src[kc * 4];
    }
    __syncthreads();

    int n = blockIdx.x * blockDim.x + tid;
    if (n >= NNODES) return;

    float acc[8];
    #pragma unroll
    for (int r = 0; r < 8; ++r) acc[r] = 0.f;

    const float4* xrow = (const float4*)&g_x[n * FDIM];
    #pragma unroll
    for (int kc = 0; kc < 16; ++kc) {
        float4 xv = xrow[kc];
        #pragma unroll
        for (int r = 0; r < 8; ++r) {
            float4 w = Wsel[r][kc];
            acc[r] += xv.x * w.x + xv.y * w.y + xv.z * w.z + xv.w * w.w;
        }
    }
    g_xr4[n]   = make_float4(acc[0], acc[1], acc[2], acc[3]);
    g_root4[n] = make_float4(acc[4], acc[5], acc[6], acc[7]);
}

// ---------------- iter-3 aggregation + readout: thread per node ----------
__global__ void agg4_kernel(const float* __restrict__ evec, float* __restrict__ out)
{
    int n = blockIdx.x * blockDim.x + threadIdx.x;
    if (n >= NNODES) return;

    float4 acc = g_root4[n];
    int e   = g_rowptr[n];
    int end = g_rowptr[n + 1];
    for (; e + 4 <= end; e += 4) {
        int s0 = g_ssrc[e],     s1 = g_ssrc[e + 1];
        int s2 = g_ssrc[e + 2], s3 = g_ssrc[e + 3];
        float4 a0 = g_xr4[s0], a1 = g_xr4[s1];
        float4 a2 = g_xr4[s2], a3 = g_xr4[s3];
        acc.x += (a0.x + a1.x) + (a2.x + a3.x);
        acc.y += (a0.y + a1.y) + (a2.y + a3.y);
        acc.z += (a0.z + a1.z) + (a2.z + a3.z);
        acc.w += (a0.w + a1.w) + (a2.w + a3.w);
    }
    for (; e < end; ++e) {
        float4 a = g_xr4[g_ssrc[e]];
        acc.x += a.x; acc.y += a.y; acc.z += a.z; acc.w += a.w;
    }
    out[n] = fmaxf(acc.x, 0.f) * evec[15] + fmaxf(acc.y, 0.f) * evec[31]
           + fmaxf(acc.z, 0.f) * evec[47] + fmaxf(acc.w, 0.f) * evec[63];
}

// ---------------- launch ----------------
extern "C" void kernel_launch(void* const* d_in, const int* in_sizes, int n_in,
                              void* d_out, int out_size) {
    const float* x = 0; const void* ei = 0;
    const float* Wrel = 0; const float* Wroot = 0; const float* evec = 0;
    for (int i = 0; i < n_in; ++i) {
        int sz = in_sizes[i];
        if (sz == NNODES * FDIM)      x = (const float*)d_in[i];
        else if (sz == 2 * NEDGES)    ei = d_in[i];
        else if (sz == FDIM * FDIM) { if (!Wrel) Wrel = (const float*)d_in[i];
                                      else       Wroot = (const float*)d_in[i]; }
        else if (sz == FDIM)          evec = (const float*)d_in[i];
    }
    float* out = (float*)d_out;

    const int GB = (NNODES + GM - 1) / GM;     // 782
    const int AB = (NNODES + 7) / 8;           // 6250
    const int TB = (NNODES + 255) / 256;       // 196

    detect_prep_kernel<<<1, 1024>>>(ei, Wrel, Wroot);
    zero_counts_kernel<<<TB, 256>>>();
    hist_kernel<<<(NEDGES + 255) / 256, 256>>>(ei);

    mma_gemm_kernel<<<GB, 256>>>(x, 1);                   // iter-1 (profiled slot)

    chunk_reduce_kernel<<<NCHUNK, 256>>>();
    partial_scan_kernel<<<1, 256>>>();
    chunk_scan_kernel<<<NCHUNK, 256>>>();
    scatter_kernel<<<(NEDGES + 255) / 256, 256>>>(ei);

    agg_kernel<<<AB, 256>>>();                            // iter 1
    mma_gemm_kernel<<<GB, 256>>>(x, 0);                   // iter 2
    agg_kernel<<<AB, 256>>>();
    gemm4_kernel<<<TB, 256>>>(Wrel, Wroot);               // iter 3 (sparse)
    agg4_kernel<<<TB, 256>>>(evec, out);
}

// round 14
// speedup vs baseline: 1.2564x; 1.0228x over previous
#include <cuda_runtime.h>

#define NNODES 50000
#define NEDGES 800000
#define FDIM   64
#define NCHUNK 196        // ceil(NNODES/256)

// ---------------- scratch (static device globals; no runtime alloc) ----------------
__device__ __align__(16) float g_x[NNODES * FDIM];     // post-relu features
__device__ __align__(16) float g_xr[NNODES * FDIM];    // x @ W_rel.T  (gathered over edges)
__device__ __align__(16) float g_root[NNODES * FDIM];  // x @ W_root.T (agg init)
__device__ float4 g_xr4[NNODES];                       // iter-3 sparse columns (rel)
__device__ float4 g_root4[NNODES];                     // iter-3 sparse columns (root)
__device__ __align__(16) float4 g_Wp[4096];            // packed tf32-split W (64KB)
__device__ int g_rowptr[NNODES + 1];
__device__ int g_cursor[NNODES];
__device__ int g_ssrc[NEDGES];
__device__ int g_partial[256];
__device__ int g_is64;

__device__ __forceinline__ unsigned f2tf32(float f) {
    unsigned u;
    asm("cvt.rna.tf32.f32 %0, %1;" : "=r"(u) : "f"(f));
    return u;
}

// ---------------- dtype detection + one-time packed W split (fused) ----------------
// g_Wp[ks*512 + n*4 + bc] = {hi(W[n][k0+bc]), hi(W[n][k0+bc+4]),
//                            lo(W[n][k0+bc]), lo(W[n][k0+bc+4])}, k0 = ks*8.
__global__ void detect_prep_kernel(const void* ei_raw,
                                   const float* __restrict__ Wrel,
                                   const float* __restrict__ Wroot) {
    __shared__ int any_nonzero;
    int t = threadIdx.x;
    if (t == 0) any_nonzero = 0;
    __syncthreads();
    const int* w = (const int*)ei_raw;
    if (w[2 * t + 1] != 0) atomicOr(&any_nonzero, 1);

    for (int i = t; i < 4096; i += 1024) {
        int ks = i >> 9, n = (i >> 2) & 127, bc = i & 3;
        int k1 = ks * 8 + bc, k2 = k1 + 4;
        const float* src = (n < 64) ? &Wrel[n * FDIM] : &Wroot[(n - 64) * FDIM];
        float v1 = src[k1], v2 = src[k2];
        float h1 = __uint_as_float(f2tf32(v1));
        float h2 = __uint_as_float(f2tf32(v2));
        float l1 = __uint_as_float(f2tf32(v1 - h1));
        float l2 = __uint_as_float(f2tf32(v2 - h2));
        g_Wp[i] = make_float4(h1, h2, l1, l2);
    }
    __syncthreads();
    if (t == 0) g_is64 = any_nonzero ? 0 : 1;
}

__device__ __forceinline__ int load_idx(const void* ei_raw, int pos, int is64) {
    if (is64) return (int)((const long long*)ei_raw)[pos];
    return ((const int*)ei_raw)[pos];
}

// ---------------- CSR build (by dst) ----------------
__global__ void zero_counts_kernel() {
    int i = blockIdx.x * blockDim.x + threadIdx.x;
    if (i < NNODES) g_cursor[i] = 0;
}

__global__ void hist_kernel(const void* __restrict__ ei_raw) {
    int e = blockIdx.x * blockDim.x + threadIdx.x;
    if (e < NEDGES) {
        int d = load_idx(ei_raw, NEDGES + e, g_is64);
        if ((unsigned)d < (unsigned)NNODES) atomicAdd(&g_cursor[d], 1);
    }
}

__global__ void chunk_reduce_kernel() {
    int i = blockIdx.x * 256 + threadIdx.x;
    int v = (i < NNODES) ? g_cursor[i] : 0;
    #pragma unroll
    for (int off = 16; off; off >>= 1) v += __shfl_down_sync(0xffffffffu, v, off);
    __shared__ int ws[8];
    if ((threadIdx.x & 31) == 0) ws[threadIdx.x >> 5] = v;
    __syncthreads();
    if (threadIdx.x < 8) {
        int s = ws[threadIdx.x];
        #pragma unroll
        for (int off = 4; off; off >>= 1) s += __shfl_down_sync(0xffu, s, off);
        if (threadIdx.x == 0) g_partial[blockIdx.x] = s;
    }
}

__global__ void partial_scan_kernel() {
    __shared__ int ps[256];
    int t = threadIdx.x;
    int v = (t < NCHUNK) ? g_partial[t] : 0;
    ps[t] = v;
    __syncthreads();
    #pragma unroll
    for (int off = 1; off < 256; off <<= 1) {
        int u = (t >= off) ? ps[t - off] : 0;
        __syncthreads();
        ps[t] += u;
        __syncthreads();
    }
    if (t < NCHUNK) g_partial[t] = ps[t] - v;
    if (t == 255) g_rowptr[NNODES] = ps[255];
}

__global__ void chunk_scan_kernel() {
    __shared__ int ps[256];
    int t = threadIdx.x;
    int i = blockIdx.x * 256 + t;
    int v = (i < NNODES) ? g_cursor[i] : 0;
    ps[t] = v;
    __syncthreads();
    #pragma unroll
    for (int off = 1; off < 256; off <<= 1) {
        int u = (t >= off) ? ps[t - off] : 0;
        __syncthreads();
        ps[t] += u;
        __syncthreads();
    }
    int excl = ps[t] - v + g_partial[blockIdx.x];
    if (i < NNODES) { g_rowptr[i] = excl; g_cursor[i] = excl; }
}

__global__ void scatter_kernel(const void* __restrict__ ei_raw) {
    int e = blockIdx.x * blockDim.x + threadIdx.x;
    if (e < NEDGES) {
        int is64 = g_is64;
        int d = load_idx(ei_raw, NEDGES + e, is64);
        int s = load_idx(ei_raw, e, is64);
        if ((unsigned)d < (unsigned)NNODES && (unsigned)s < (unsigned)NNODES) {
            int p = atomicAdd(&g_cursor[d], 1);
            g_ssrc[p] = s;
        }
    }
}

// ---------------- split-tf32 tensor GEMM: [xr | root] = x @ [W_rel | W_root].T ---------
// Block 64 nodes x 128 outputs x K=64. 8 warps, warp tile 32M x 32N.
// A packed in smem layout [ks][node][u] (stride 260 quads/ks): STS.128/LDS.128
// phases all-banks-distinct. B packed in global g_Wp (L1-hot).
#define GM 64

__global__ void __launch_bounds__(256)
mma_gemm_kernel(const float* __restrict__ xext, int first)
{
    __shared__ float4 Xa[8 * 260];     // 33280 B static

    const float* xin = first ? xext : g_x;
    int tid = threadIdx.x;
    int nbase = blockIdx.x * GM;

    // ---- prologue: thread (u = tid&3, n = tid>>2); 8 STS.128, zero conflicts ----
    {
        int u = tid & 3;
        int n = tid >> 2;
        int gn = nbase + n;
        if (gn < NNODES) {
            const float* row = &xin[gn * FDIM];
            #pragma unroll
            for (int ks = 0; ks < 8; ++ks) {
                float v1 = row[ks * 8 + u];
                float v2 = row[ks * 8 + 4 + u];
                float h1 = __uint_as_float(f2tf32(v1));
                float h2 = __uint_as_float(f2tf32(v2));
                float l1 = __uint_as_float(f2tf32(v1 - h1));
                float l2 = __uint_as_float(f2tf32(v2 - h2));
                Xa[ks * 260 + n * 4 + u] = make_float4(h1, h2, l1, l2);
            }
        } else {
            #pragma unroll
            for (int ks = 0; ks < 8; ++ks)
                Xa[ks * 260 + n * 4 + u] = make_float4(0.f, 0.f, 0.f, 0.f);
        }
    }
    __syncthreads();

    int warp = tid >> 5;
    int lane = tid & 31;
    int m0 = (warp >> 2) * 32;         // 0 or 32
    int n0 = (warp & 3) * 32;          // 0,32,64,96
    int r  = lane >> 2;                // 0..7
    int ac = lane & 3;                 // 0..3

    float c[2][4][4];
    #pragma unroll
    for (int t = 0; t < 2; ++t)
        #pragma unroll
        for (int j = 0; j < 4; ++j)
            #pragma unroll
            for (int q = 0; q < 4; ++q) c[t][j][q] = 0.f;

    int ra = m0 + r;
    #pragma unroll
    for (int ks = 0; ks < 8; ++ks) {
        float4 a0 = Xa[ks * 260 + (ra)      * 4 + ac];
        float4 a1 = Xa[ks * 260 + (ra + 8)  * 4 + ac];
        float4 a2 = Xa[ks * 260 + (ra + 16) * 4 + ac];
        float4 a3 = Xa[ks * 260 + (ra + 24) * 4 + ac];
        unsigned ahi[2][4], alo[2][4];
        ahi[0][0] = __float_as_uint(a0.x); ahi[0][1] = __float_as_uint(a1.x);
        ahi[0][2] = __float_as_uint(a0.y); ahi[0][3] = __float_as_uint(a1.y);
        alo[0][0] = __float_as_uint(a0.z); alo[0][1] = __float_as_uint(a1.z);
        alo[0][2] = __float_as_uint(a0.w); alo[0][3] = __float_as_uint(a1.w);
        ahi[1][0] = __float_as_uint(a2.x); ahi[1][1] = __float_as_uint(a3.x);
        ahi[1][2] = __float_as_uint(a2.y); ahi[1][3] = __float_as_uint(a3.y);
        alo[1][0] = __float_as_uint(a2.z); alo[1][1] = __float_as_uint(a3.z);
        alo[1][2] = __float_as_uint(a2.w); alo[1][3] = __float_as_uint(a3.w);
        #pragma unroll
        for (int j = 0; j < 4; ++j) {
            int n = n0 + j * 8 + r;
            float4 b = __ldg(&g_Wp[ks * 512 + n * 4 + ac]);
            unsigned bh0 = __float_as_uint(b.x), bh1 = __float_as_uint(b.y);
            unsigned bl0 = __float_as_uint(b.z), bl1 = __float_as_uint(b.w);
            #pragma unroll
            for (int t = 0; t < 2; ++t) {
                asm("mma.sync.aligned.m16n8k8.row.col.f32.tf32.tf32.f32 "
                    "{%0,%1,%2,%3}, {%4,%5,%6,%7}, {%8,%9}, {%0,%1,%2,%3};"
                    : "+f"(c[t][j][0]), "+f"(c[t][j][1]), "+f"(c[t][j][2]), "+f"(c[t][j][3])
                    : "r"(ahi[t][0]), "r"(ahi[t][1]), "r"(ahi[t][2]), "r"(ahi[t][3]),
                      "r"(bh0), "r"(bh1));
                asm("mma.sync.aligned.m16n8k8.row.col.f32.tf32.tf32.f32 "
                    "{%0,%1,%2,%3}, {%4,%5,%6,%7}, {%8,%9}, {%0,%1,%2,%3};"
                    : "+f"(c[t][j][0]), "+f"(c[t][j][1]), "+f"(c[t][j][2]), "+f"(c[t][j][3])
                    : "r"(ahi[t][0]), "r"(ahi[t][1]), "r"(ahi[t][2]), "r"(ahi[t][3]),
                      "r"(bl0), "r"(bl1));
                asm("mma.sync.aligned.m16n8k8.row.col.f32.tf32.tf32.f32 "
                    "{%0,%1,%2,%3}, {%4,%5,%6,%7}, {%8,%9}, {%0,%1,%2,%3};"
                    : "+f"(c[t][j][0]), "+f"(c[t][j][1]), "+f"(c[t][j][2]), "+f"(c[t][j][3])
                    : "r"(alo[t][0]), "r"(alo[t][1]), "r"(alo[t][2]), "r"(alo[t][3]),
                      "r"(bh0), "r"(bh1));
            }
        }
    }

    float* dst;
    int col0;
    if (n0 < 64) { dst = g_xr;   col0 = n0; }
    else         { dst = g_root; col0 = n0 - 64; }
    #pragma unroll
    for (int t = 0; t < 2; ++t) {
        int nodeA = nbase + m0 + 16 * t + r;
        int nodeB = nodeA + 8;
        #pragma unroll
        for (int j = 0; j < 4; ++j) {
            int col = col0 + j * 8 + 2 * ac;
            if (nodeA < NNODES)
                *(float2*)&dst[nodeA * FDIM + col] = make_float2(c[t][j][0], c[t][j][1]);
            if (nodeB < NNODES)
                *(float2*)&dst[nodeB * FDIM + col] = make_float2(c[t][j][2], c[t][j][3]);
        }
    }
}

// ---------------- full aggregation (iters 1,2): warp per node, float2 per lane ---------
__global__ void agg_kernel()
{
    int gw   = (blockIdx.x * blockDim.x + threadIdx.x) >> 5;
    int lane = threadIdx.x & 31;
    if (gw >= NNODES) return;

    const float2* __restrict__ xr2 = (const float2*)g_xr;
    float2 acc = *(const float2*)&g_root[gw * FDIM + lane * 2];

    int e   = g_rowptr[gw];
    int end = g_rowptr[gw + 1];
    for (; e + 8 <= end; e += 8) {
        int s[8];
        #pragma unroll
        for (int q = 0; q < 8; ++q) s[q] = g_ssrc[e + q];
        float2 a[8];
        #pragma unroll
        for (int q = 0; q < 8; ++q) a[q] = xr2[s[q] * 32 + lane];
        #pragma unroll
        for (int q = 0; q < 8; ++q) { acc.x += a[q].x; acc.y += a[q].y; }
    }
    for (; e < end; ++e) {
        int sv = g_ssrc[e];
        float2 a = xr2[sv * 32 + lane];
        acc.x += a.x;
        acc.y += a.y;
    }
    acc.x = fmaxf(acc.x, 0.f);
    acc.y = fmaxf(acc.y, 0.f);
    *(float2*)&g_x[gw * FDIM + lane * 2] = acc;
}

// ---------------- iter-3 sparse GEMM: only readout features {15,31,47,63} --------------
__constant__ int c_pos[4] = {15, 31, 47, 63};

__global__ void gemm4_kernel(const float* __restrict__ Wrel,
                             const float* __restrict__ Wroot)
{
    __shared__ float4 Wsel[8][16];
    int tid = threadIdx.x;
    if (tid < 128) {
        int r = tid >> 4, kc = tid & 15;
        const float* src = (r < 4) ? &Wrel[c_pos[r] * FDIM] : &Wroot[c_pos[r - 4] * FDIM];
        Wsel[r][kc] = *(const float4*)&src[kc * 4];
    }
    __syncthreads();

    int n = blockIdx.x * blockDim.x + tid;
    if (n >= NNODES) return;

    float acc[8];
    #pragma unroll
    for (int r = 0; r < 8; ++r) acc[r] = 0.f;

    const float4* xrow = (const float4*)&g_x[n * FDIM];
    #pragma unroll
    for (int kc = 0; kc < 16; ++kc) {
        float4 xv = xrow[kc];
        #pragma unroll
        for (int r = 0; r < 8; ++r) {
            float4 w = Wsel[r][kc];
            acc[r] += xv.x * w.x + xv.y * w.y + xv.z * w.z + xv.w * w.w;
        }
    }
    g_xr4[n]   = make_float4(acc[0], acc[1], acc[2], acc[3]);
    g_root4[n] = make_float4(acc[4], acc[5], acc[6], acc[7]);
}

// ---------------- iter-3 aggregation + readout: thread per node ----------
__global__ void agg4_kernel(const float* __restrict__ evec, float* __restrict__ out)
{
    int n = blockIdx.x * blockDim.x + threadIdx.x;
    if (n >= NNODES) return;

    float4 acc = g_root4[n];
    int e   = g_rowptr[n];
    int end = g_rowptr[n + 1];
    for (; e + 4 <= end; e += 4) {
        int s0 = g_ssrc[e],     s1 = g_ssrc[e + 1];
        int s2 = g_ssrc[e + 2], s3 = g_ssrc[e + 3];
        float4 a0 = g_xr4[s0], a1 = g_xr4[s1];
        float4 a2 = g_xr4[s2], a3 = g_xr4[s3];
        acc.x += (a0.x + a1.x) + (a2.x + a3.x);
        acc.y += (a0.y + a1.y) + (a2.y + a3.y);
        acc.z += (a0.z + a1.z) + (a2.z + a3.z);
        acc.w += (a0.w + a1.w) + (a2.w + a3.w);
    }
    for (; e < end; ++e) {
        float4 a = g_xr4[g_ssrc[e]];
        acc.x += a.x; acc.y += a.y; acc.z += a.z; acc.w += a.w;
    }
    out[n] = fmaxf(acc.x, 0.f) * evec[15] + fmaxf(acc.y, 0.f) * evec[31]
           + fmaxf(acc.z, 0.f) * evec[47] + fmaxf(acc.w, 0.f) * evec[63];
}

// ---------------- launch (single stream; proven capture-safe topology) ----------------
extern "C" void kernel_launch(void* const* d_in, const int* in_sizes, int n_in,
                              void* d_out, int out_size) {
    const float* x = 0; const void* ei = 0;
    const float* Wrel = 0; const float* Wroot = 0; const float* evec = 0;
    for (int i = 0; i < n_in; ++i) {
        int sz = in_sizes[i];
        if (sz == NNODES * FDIM)      x = (const float*)d_in[i];
        else if (sz == 2 * NEDGES)    ei = d_in[i];
        else if (sz == FDIM * FDIM) { if (!Wrel) Wrel = (const float*)d_in[i];
                                      else       Wroot = (const float*)d_in[i]; }
        else if (sz == FDIM)          evec = (const float*)d_in[i];
    }
    float* out = (float*)d_out;

    const int GB = (NNODES + GM - 1) / GM;     // 782
    const int AB = (NNODES + 7) / 8;           // 6250
    const int TB = (NNODES + 255) / 256;       // 196

    detect_prep_kernel<<<1, 1024>>>(ei, Wrel, Wroot);
    zero_counts_kernel<<<TB, 256>>>();
    hist_kernel<<<(NEDGES + 255) / 256, 256>>>(ei);

    mma_gemm_kernel<<<GB, 256>>>(x, 1);                   // iter-1 (profiled slot)

    chunk_reduce_kernel<<<NCHUNK, 256>>>();
    partial_scan_kernel<<<1, 256>>>();
    chunk_scan_kernel<<<NCHUNK, 256>>>();
    scatter_kernel<<<(NEDGES + 255) / 256, 256>>>(ei);

    agg_kernel<<<AB, 256>>>();                            // iter 1
    mma_gemm_kernel<<<GB, 256>>>(x, 0);                   // iter 2
    agg_kernel<<<AB, 256>>>();
    gemm4_kernel<<<TB, 256>>>(Wrel, Wroot);               // iter 3 (sparse)
    agg4_kernel<<<TB, 256>>>(evec, out);
}

// round 15
// speedup vs baseline: 1.2766x; 1.0161x over previous
#include <cuda_runtime.h>
#include <cuda_fp16.h>

#define NNODES 50000
#define NEDGES 800000
#define FDIM   64
#define NCHUNK 196        // ceil(NNODES/256)

// ---------------- scratch (static device globals; no runtime alloc) ----------------
__device__ __align__(16) float   g_x[NNODES * FDIM];    // post-relu features
__device__ __align__(16) __half2 g_xrh[NNODES * 32];    // x @ W_rel.T in fp16 (gathered)
__device__ __align__(16) float   g_root[NNODES * FDIM]; // x @ W_root.T (agg init)
__device__ float4 g_xr4[NNODES];                        // iter-3 sparse columns (rel)
__device__ float4 g_root4[NNODES];                      // iter-3 sparse columns (root)
__device__ __align__(16) float4 g_Wp[4096];             // packed tf32-split W (64KB)
__device__ int g_rowptr[NNODES + 1];
__device__ int g_cursor[NNODES];
__device__ int g_ssrc[NEDGES];
__device__ int g_partial[256];
__device__ int g_is64;

__device__ __forceinline__ unsigned f2tf32(float f) {
    unsigned u;
    asm("cvt.rna.tf32.f32 %0, %1;" : "=r"(u) : "f"(f));
    return u;
}

// ---------------- dtype detection ----------------
__global__ void detect_kernel(const void* ei_raw) {
    __shared__ int any_nonzero;
    int t = threadIdx.x;
    if (t == 0) any_nonzero = 0;
    __syncthreads();
    const int* w = (const int*)ei_raw;
    if (w[2 * t + 1] != 0) atomicOr(&any_nonzero, 1);
    __syncthreads();
    if (t == 0) g_is64 = any_nonzero ? 0 : 1;
}

// ---------------- one-time packed W split (parallel) ----------------
// g_Wp[ks*512 + n*4 + bc] = {hi(W[n][k0+bc]), hi(W[n][k0+bc+4]),
//                            lo(W[n][k0+bc]), lo(W[n][k0+bc+4])}, k0 = ks*8.
__global__ void wprep_kernel(const float* __restrict__ Wrel,
                             const float* __restrict__ Wroot) {
    int i = blockIdx.x * blockDim.x + threadIdx.x;
    if (i >= 4096) return;
    int ks = i >> 9, n = (i >> 2) & 127, bc = i & 3;
    int k1 = ks * 8 + bc, k2 = k1 + 4;
    const float* src = (n < 64) ? &Wrel[n * FDIM] : &Wroot[(n - 64) * FDIM];
    float v1 = src[k1], v2 = src[k2];
    float h1 = __uint_as_float(f2tf32(v1));
    float h2 = __uint_as_float(f2tf32(v2));
    float l1 = __uint_as_float(f2tf32(v1 - h1));
    float l2 = __uint_as_float(f2tf32(v2 - h2));
    g_Wp[i] = make_float4(h1, h2, l1, l2);
}

__device__ __forceinline__ int load_idx(const void* ei_raw, int pos, int is64) {
    if (is64) return (int)((const long long*)ei_raw)[pos];
    return ((const int*)ei_raw)[pos];
}

// ---------------- CSR build (by dst) ----------------
__global__ void zero_counts_kernel() {
    int i = blockIdx.x * blockDim.x + threadIdx.x;
    if (i < NNODES) g_cursor[i] = 0;
}

__global__ void hist_kernel(const void* __restrict__ ei_raw) {
    int e = blockIdx.x * blockDim.x + threadIdx.x;
    if (e < NEDGES) {
        int d = load_idx(ei_raw, NEDGES + e, g_is64);
        if ((unsigned)d < (unsigned)NNODES) atomicAdd(&g_cursor[d], 1);
    }
}

__global__ void chunk_reduce_kernel() {
    int i = blockIdx.x * 256 + threadIdx.x;
    int v = (i < NNODES) ? g_cursor[i] : 0;
    #pragma unroll
    for (int off = 16; off; off >>= 1) v += __shfl_down_sync(0xffffffffu, v, off);
    __shared__ int ws[8];
    if ((threadIdx.x & 31) == 0) ws[threadIdx.x >> 5] = v;
    __syncthreads();
    if (threadIdx.x < 8) {
        int s = ws[threadIdx.x];
        #pragma unroll
        for (int off = 4; off; off >>= 1) s += __shfl_down_sync(0xffu, s, off);
        if (threadIdx.x == 0) g_partial[blockIdx.x] = s;
    }
}

__global__ void partial_scan_kernel() {
    __shared__ int ps[256];
    int t = threadIdx.x;
    int v = (t < NCHUNK) ? g_partial[t] : 0;
    ps[t] = v;
    __syncthreads();
    #pragma unroll
    for (int off = 1; off < 256; off <<= 1) {
        int u = (t >= off) ? ps[t - off] : 0;
        __syncthreads();
        ps[t] += u;
        __syncthreads();
    }
    if (t < NCHUNK) g_partial[t] = ps[t] - v;
    if (t == 255) g_rowptr[NNODES] = ps[255];
}

__global__ void chunk_scan_kernel() {
    __shared__ int ps[256];
    int t = threadIdx.x;
    int i = blockIdx.x * 256 + t;
    int v = (i < NNODES) ? g_cursor[i] : 0;
    ps[t] = v;
    __syncthreads();
    #pragma unroll
    for (int off = 1; off < 256; off <<= 1) {
        int u = (t >= off) ? ps[t - off] : 0;
        __syncthreads();
        ps[t] += u;
        __syncthreads();
    }
    int excl = ps[t] - v + g_partial[blockIdx.x];
    if (i < NNODES) { g_rowptr[i] = excl; g_cursor[i] = excl; }
}

__global__ void scatter_kernel(const void* __restrict__ ei_raw) {
    int e = blockIdx.x * blockDim.x + threadIdx.x;
    if (e < NEDGES) {
        int is64 = g_is64;
        int d = load_idx(ei_raw, NEDGES + e, is64);
        int s = load_idx(ei_raw, e, is64);
        if ((unsigned)d < (unsigned)NNODES && (unsigned)s < (unsigned)NNODES) {
            int p = atomicAdd(&g_cursor[d], 1);
            g_ssrc[p] = s;
        }
    }
}

// ---------------- split-tf32 tensor GEMM: [xr(h) | root] = x @ [W_rel | W_root].T ------
// Block 64 nodes x 128 outputs x K=64. 8 warps, warp tile 32M x 32N.
// A packed in smem [ks][node][u] (stride 260 quads): conflict-free STS/LDS.128.
// B packed in global g_Wp (L1-hot). xr half writes fp16, root half fp32.
#define GM 64

__global__ void __launch_bounds__(256)
mma_gemm_kernel(const float* __restrict__ xext, int first)
{
    __shared__ float4 Xa[8 * 260];     // 33280 B static

    const float* xin = first ? xext : g_x;
    int tid = threadIdx.x;
    int nbase = blockIdx.x * GM;

    // ---- prologue: thread (u = tid&3, n = tid>>2); 8 STS.128, zero conflicts ----
    {
        int u = tid & 3;
        int n = tid >> 2;
        int gn = nbase + n;
        if (gn < NNODES) {
            const float* row = &xin[gn * FDIM];
            #pragma unroll
            for (int ks = 0; ks < 8; ++ks) {
                float v1 = row[ks * 8 + u];
                float v2 = row[ks * 8 + 4 + u];
                float h1 = __uint_as_float(f2tf32(v1));
                float h2 = __uint_as_float(f2tf32(v2));
                float l1 = __uint_as_float(f2tf32(v1 - h1));
                float l2 = __uint_as_float(f2tf32(v2 - h2));
                Xa[ks * 260 + n * 4 + u] = make_float4(h1, h2, l1, l2);
            }
        } else {
            #pragma unroll
            for (int ks = 0; ks < 8; ++ks)
                Xa[ks * 260 + n * 4 + u] = make_float4(0.f, 0.f, 0.f, 0.f);
        }
    }
    __syncthreads();

    int warp = tid >> 5;
    int lane = tid & 31;
    int m0 = (warp >> 2) * 32;         // 0 or 32
    int n0 = (warp & 3) * 32;          // 0,32,64,96
    int r  = lane >> 2;                // 0..7
    int ac = lane & 3;                 // 0..3

    float c[2][4][4];
    #pragma unroll
    for (int t = 0; t < 2; ++t)
        #pragma unroll
        for (int j = 0; j < 4; ++j)
            #pragma unroll
            for (int q = 0; q < 4; ++q) c[t][j][q] = 0.f;

    int ra = m0 + r;
    #pragma unroll
    for (int ks = 0; ks < 8; ++ks) {
        float4 a0 = Xa[ks * 260 + (ra)      * 4 + ac];
        float4 a1 = Xa[ks * 260 + (ra + 8)  * 4 + ac];
        float4 a2 = Xa[ks * 260 + (ra + 16) * 4 + ac];
        float4 a3 = Xa[ks * 260 + (ra + 24) * 4 + ac];
        unsigned ahi[2][4], alo[2][4];
        ahi[0][0] = __float_as_uint(a0.x); ahi[0][1] = __float_as_uint(a1.x);
        ahi[0][2] = __float_as_uint(a0.y); ahi[0][3] = __float_as_uint(a1.y);
        alo[0][0] = __float_as_uint(a0.z); alo[0][1] = __float_as_uint(a1.z);
        alo[0][2] = __float_as_uint(a0.w); alo[0][3] = __float_as_uint(a1.w);
        ahi[1][0] = __float_as_uint(a2.x); ahi[1][1] = __float_as_uint(a3.x);
        ahi[1][2] = __float_as_uint(a2.y); ahi[1][3] = __float_as_uint(a3.y);
        alo[1][0] = __float_as_uint(a2.z); alo[1][1] = __float_as_uint(a3.z);
        alo[1][2] = __float_as_uint(a2.w); alo[1][3] = __float_as_uint(a3.w);
        #pragma unroll
        for (int j = 0; j < 4; ++j) {
            int n = n0 + j * 8 + r;
            float4 b = __ldg(&g_Wp[ks * 512 + n * 4 + ac]);
            unsigned bh0 = __float_as_uint(b.x), bh1 = __float_as_uint(b.y);
            unsigned bl0 = __float_as_uint(b.z), bl1 = __float_as_uint(b.w);
            #pragma unroll
            for (int t = 0; t < 2; ++t) {
                asm("mma.sync.aligned.m16n8k8.row.col.f32.tf32.tf32.f32 "
                    "{%0,%1,%2,%3}, {%4,%5,%6,%7}, {%8,%9}, {%0,%1,%2,%3};"
                    : "+f"(c[t][j][0]), "+f"(c[t][j][1]), "+f"(c[t][j][2]), "+f"(c[t][j][3])
                    : "r"(ahi[t][0]), "r"(ahi[t][1]), "r"(ahi[t][2]), "r"(ahi[t][3]),
                      "r"(bh0), "r"(bh1));
                asm("mma.sync.aligned.m16n8k8.row.col.f32.tf32.tf32.f32 "
                    "{%0,%1,%2,%3}, {%4,%5,%6,%7}, {%8,%9}, {%0,%1,%2,%3};"
                    : "+f"(c[t][j][0]), "+f"(c[t][j][1]), "+f"(c[t][j][2]), "+f"(c[t][j][3])
                    : "r"(ahi[t][0]), "r"(ahi[t][1]), "r"(ahi[t][2]), "r"(ahi[t][3]),
                      "r"(bl0), "r"(bl1));
                asm("mma.sync.aligned.m16n8k8.row.col.f32.tf32.tf32.f32 "
                    "{%0,%1,%2,%3}, {%4,%5,%6,%7}, {%8,%9}, {%0,%1,%2,%3};"
                    : "+f"(c[t][j][0]), "+f"(c[t][j][1]), "+f"(c[t][j][2]), "+f"(c[t][j][3])
                    : "r"(alo[t][0]), "r"(alo[t][1]), "r"(alo[t][2]), "r"(alo[t][3]),
                      "r"(bh0), "r"(bh1));
            }
        }
    }

    if (n0 < 64) {
        // xr half -> fp16 (halves agg gather traffic)
        #pragma unroll
        for (int t = 0; t < 2; ++t) {
            int nodeA = nbase + m0 + 16 * t + r;
            int nodeB = nodeA + 8;
            #pragma unroll
            for (int j = 0; j < 4; ++j) {
                int cp = (n0 + j * 8 + 2 * ac) >> 1;   // half2 slot
                if (nodeA < NNODES)
                    g_xrh[nodeA * 32 + cp] = __floats2half2_rn(c[t][j][0], c[t][j][1]);
                if (nodeB < NNODES)
                    g_xrh[nodeB * 32 + cp] = __floats2half2_rn(c[t][j][2], c[t][j][3]);
            }
        }
    } else {
        int col0 = n0 - 64;
        #pragma unroll
        for (int t = 0; t < 2; ++t) {
            int nodeA = nbase + m0 + 16 * t + r;
            int nodeB = nodeA + 8;
            #pragma unroll
            for (int j = 0; j < 4; ++j) {
                int col = col0 + j * 8 + 2 * ac;
                if (nodeA < NNODES)
                    *(float2*)&g_root[nodeA * FDIM + col] = make_float2(c[t][j][0], c[t][j][1]);
                if (nodeB < NNODES)
                    *(float2*)&g_root[nodeB * FDIM + col] = make_float2(c[t][j][2], c[t][j][3]);
            }
        }
    }
}

// ---------------- full aggregation (iters 1,2): warp per node, half2 per lane ----------
__global__ void agg_kernel()
{
    int gw   = (blockIdx.x * blockDim.x + threadIdx.x) >> 5;
    int lane = threadIdx.x & 31;
    if (gw >= NNODES) return;

    float2 acc = *(const float2*)&g_root[gw * FDIM + lane * 2];

    int e   = g_rowptr[gw];
    int end = g_rowptr[gw + 1];
    for (; e + 8 <= end; e += 8) {
        int s[8];
        #pragma unroll
        for (int q = 0; q < 8; ++q) s[q] = g_ssrc[e + q];
        __half2 h[8];
        #pragma unroll
        for (int q = 0; q < 8; ++q) h[q] = g_xrh[s[q] * 32 + lane];
        #pragma unroll
        for (int q = 0; q < 8; ++q) {
            float2 a = __half22float2(h[q]);
            acc.x += a.x; acc.y += a.y;
        }
    }
    for (; e < end; ++e) {
        float2 a = __half22float2(g_xrh[g_ssrc[e] * 32 + lane]);
        acc.x += a.x;
        acc.y += a.y;
    }
    acc.x = fmaxf(acc.x, 0.f);
    acc.y = fmaxf(acc.y, 0.f);
    *(float2*)&g_x[gw * FDIM + lane * 2] = acc;
}

// ---------------- iter-3 sparse GEMM: only readout features {15,31,47,63} --------------
__constant__ int c_pos[4] = {15, 31, 47, 63};

__global__ void gemm4_kernel(const float* __restrict__ Wrel,
                             const float* __restrict__ Wroot)
{
    __shared__ float4 Wsel[8][16];
    int tid = threadIdx.x;
    if (tid < 128) {
        int r = tid >> 4, kc = tid & 15;
        const float* src = (r < 4) ? &Wrel[c_pos[r] * FDIM] : &Wroot[c_pos[r - 4] * FDIM];
        Wsel[r][kc] = *(const float4*)&src[kc * 4];
    }
    __syncthreads();

    int n = blockIdx.x * blockDim.x + tid;
    if (n >= NNODES) return;

    float acc[8];
    #pragma unroll
    for (int r = 0; r < 8; ++r) acc[r] = 0.f;

    const float4* xrow = (const float4*)&g_x[n * FDIM];
    #pragma unroll
    for (int kc = 0; kc < 16; ++kc) {
        float4 xv = xrow[kc];
        #pragma unroll
        for (int r = 0; r < 8; ++r) {
            float4 w = Wsel[r][kc];
            acc[r] += xv.x * w.x + xv.y * w.y + xv.z * w.z + xv.w * w.w;
        }
    }
    g_xr4[n]   = make_float4(acc[0], acc[1], acc[2], acc[3]);
    g_root4[n] = make_float4(acc[4], acc[5], acc[6], acc[7]);
}

// ---------------- iter-3 aggregation + readout: thread per node ----------
__global__ void agg4_kernel(const float* __restrict__ evec, float* __restrict__ out)
{
    int n = blockIdx.x * blockDim.x + threadIdx.x;
    if (n >= NNODES) return;

    float4 acc = g_root4[n];
    int e   = g_rowptr[n];
    int end = g_rowptr[n + 1];
    for (; e + 4 <= end; e += 4) {
        int s0 = g_ssrc[e],     s1 = g_ssrc[e + 1];
        int s2 = g_ssrc[e + 2], s3 = g_ssrc[e + 3];
        float4 a0 = g_xr4[s0], a1 = g_xr4[s1];
        float4 a2 = g_xr4[s2], a3 = g_xr4[s3];
        acc.x += (a0.x + a1.x) + (a2.x + a3.x);
        acc.y += (a0.y + a1.y) + (a2.y + a3.y);
        acc.z += (a0.z + a1.z) + (a2.z + a3.z);
        acc.w += (a0.w + a1.w) + (a2.w + a3.w);
    }
    for (; e < end; ++e) {
        float4 a = g_xr4[g_ssrc[e]];
        acc.x += a.x; acc.y += a.y; acc.z += a.z; acc.w += a.w;
    }
    out[n] = fmaxf(acc.x, 0.f) * evec[15] + fmaxf(acc.y, 0.f) * evec[31]
           + fmaxf(acc.z, 0.f) * evec[47] + fmaxf(acc.w, 0.f) * evec[63];
}

// ---------------- launch (single stream; capture-safe) ----------------
extern "C" void kernel_launch(void* const* d_in, const int* in_sizes, int n_in,
                              void* d_out, int out_size) {
    const float* x = 0; const void* ei = 0;
    const float* Wrel = 0; const float* Wroot = 0; const float* evec = 0;
    for (int i = 0; i < n_in; ++i) {
        int sz = in_sizes[i];
        if (sz == NNODES * FDIM)      x = (const float*)d_in[i];
        else if (sz == 2 * NEDGES)    ei = d_in[i];
        else if (sz == FDIM * FDIM) { if (!Wrel) Wrel = (const float*)d_in[i];
                                      else       Wroot = (const float*)d_in[i]; }
        else if (sz == FDIM)          evec = (const float*)d_in[i];
    }
    float* out = (float*)d_out;

    const int GB = (NNODES + GM - 1) / GM;     // 782
    const int AB = (NNODES + 7) / 8;           // 6250
    const int TB = (NNODES + 255) / 256;       // 196

    detect_kernel<<<1, 1024>>>(ei);
    wprep_kernel<<<16, 256>>>(Wrel, Wroot);
    zero_counts_kernel<<<TB, 256>>>();

    mma_gemm_kernel<<<GB, 256>>>(x, 1);                   // iter-1 (profiled slot)

    hist_kernel<<<(NEDGES + 255) / 256, 256>>>(ei);
    chunk_reduce_kernel<<<NCHUNK, 256>>>();
    partial_scan_kernel<<<1, 256>>>();
    chunk_scan_kernel<<<NCHUNK, 256>>>();
    scatter_kernel<<<(NEDGES + 255) / 256, 256>>>(ei);

    agg_kernel<<<AB, 256>>>();                            // iter 1
    mma_gemm_kernel<<<GB, 256>>>(x, 0);                   // iter 2
    agg_kernel<<<AB, 256>>>();
    gemm4_kernel<<<TB, 256>>>(Wrel, Wroot);               // iter 3 (sparse)
    agg4_kernel<<<TB, 256>>>(evec, out);
}

// round 16
// speedup vs baseline: 1.3415x; 1.0508x over previous
#include <cuda_runtime.h>
#include <cuda_fp16.h>

#define NNODES 50000
#define NEDGES 800000
#define FDIM   64
#define NCHUNK 196        // ceil(NNODES/256)

// ---------------- scratch (static device globals; no runtime alloc) ----------------
__device__ __align__(16) float   g_x[NNODES * FDIM];    // post-relu features (iter1 only)
__device__ __align__(16) __half2 g_xrh[NNODES * 32];    // x @ W_rel.T in fp16 (gathered)
__device__ __align__(16) float   g_root[NNODES * FDIM]; // x @ W_root.T (agg init)
__device__ float4 g_xr4[NNODES];                        // iter-3 sparse columns (rel)
__device__ float4 g_root4[NNODES];                      // iter-3 sparse columns (root)
__device__ __align__(16) float4 g_Wp[4096];             // packed tf32-split W (64KB)
__device__ int g_rowptr[NNODES];                        // CSR row starts (chunk-relative bases)
__device__ int g_cnt[NNODES];                           // per-node edge counts (row lengths)
__device__ int g_cursor[NNODES];
__device__ int g_ssrc[NEDGES];
__device__ int g_scan_ctr;
__device__ int g_is64;

__constant__ int c_pos[4] = {15, 31, 47, 63};

__device__ __forceinline__ unsigned f2tf32(float f) {
    unsigned u;
    asm("cvt.rna.tf32.f32 %0, %1;" : "=r"(u) : "f"(f));
    return u;
}

// ---------------- fused prep: W split (blocks 0-15), zero counts (16-211), detect (212) -
__global__ void prep_kernel(const void* ei_raw,
                            const float* __restrict__ Wrel,
                            const float* __restrict__ Wroot) {
    int b = blockIdx.x, t = threadIdx.x;
    if (b < 16) {
        int i = b * 256 + t;               // 0..4095
        int ks = i >> 9, n = (i >> 2) & 127, bc = i & 3;
        int k1 = ks * 8 + bc, k2 = k1 + 4;
        const float* src = (n < 64) ? &Wrel[n * FDIM] : &Wroot[(n - 64) * FDIM];
        float v1 = src[k1], v2 = src[k2];
        float h1 = __uint_as_float(f2tf32(v1));
        float h2 = __uint_as_float(f2tf32(v2));
        float l1 = __uint_as_float(f2tf32(v1 - h1));
        float l2 = __uint_as_float(f2tf32(v2 - h2));
        g_Wp[i] = make_float4(h1, h2, l1, l2);
    } else if (b < 212) {
        int i = (b - 16) * 256 + t;
        if (i < NNODES) g_cnt[i] = 0;
    } else {
        // detect: odd int32 words of first 1024 "int64" entries all zero <=> int64
        __shared__ int any_nonzero;
        if (t == 0) { any_nonzero = 0; g_scan_ctr = 0; }
        __syncthreads();
        const int* w = (const int*)ei_raw;
        #pragma unroll
        for (int q = 0; q < 4; ++q)
            if (w[2 * (t + q * 256) + 1] != 0) atomicOr(&any_nonzero, 1);
        __syncthreads();
        if (t == 0) g_is64 = any_nonzero ? 0 : 1;
    }
}

__device__ __forceinline__ int load_idx(const void* ei_raw, int pos, int is64) {
    if (is64) return (int)((const long long*)ei_raw)[pos];
    return ((const int*)ei_raw)[pos];
}

// ---------------- CSR build (by dst) ----------------
__global__ void hist_kernel(const void* __restrict__ ei_raw) {
    int e = blockIdx.x * blockDim.x + threadIdx.x;
    if (e < NEDGES) {
        int d = load_idx(ei_raw, NEDGES + e, g_is64);
        if ((unsigned)d < (unsigned)NNODES) atomicAdd(&g_cnt[d], 1);
    }
}

// single-pass scan: block-local inclusive scan + atomic global base.
// rowptr is chunk-wise non-monotone; row end = rowptr[n] + g_cnt[n].
__global__ void scan_kernel() {
    __shared__ int ps[256];
    __shared__ int base;
    int t = threadIdx.x;
    int i = blockIdx.x * 256 + t;
    int v = (i < NNODES) ? g_cnt[i] : 0;
    ps[t] = v;
    __syncthreads();
    #pragma unroll
    for (int off = 1; off < 256; off <<= 1) {
        int u = (t >= off) ? ps[t - off] : 0;
        __syncthreads();
        ps[t] += u;
        __syncthreads();
    }
    if (t == 255) base = atomicAdd(&g_scan_ctr, ps[255]);
    __syncthreads();
    int excl = base + ps[t] - v;
    if (i < NNODES) { g_rowptr[i] = excl; g_cursor[i] = excl; }
}

__global__ void scatter_kernel(const void* __restrict__ ei_raw) {
    int e = blockIdx.x * blockDim.x + threadIdx.x;
    if (e < NEDGES) {
        int is64 = g_is64;
        int d = load_idx(ei_raw, NEDGES + e, is64);
        int s = load_idx(ei_raw, e, is64);
        if ((unsigned)d < (unsigned)NNODES && (unsigned)s < (unsigned)NNODES) {
            int p = atomicAdd(&g_cursor[d], 1);
            g_ssrc[p] = s;
        }
    }
}

// ---------------- split-tf32 tensor GEMM: [xr(h) | root] = x @ [W_rel | W_root].T ------
#define GM 64

__global__ void __launch_bounds__(256)
mma_gemm_kernel(const float* __restrict__ xext, int first)
{
    __shared__ float4 Xa[8 * 260];     // 33280 B static

    const float* xin = first ? xext : g_x;
    int tid = threadIdx.x;
    int nbase = blockIdx.x * GM;

    {
        int u = tid & 3;
        int n = tid >> 2;
        int gn = nbase + n;
        if (gn < NNODES) {
            const float* row = &xin[gn * FDIM];
            #pragma unroll
            for (int ks = 0; ks < 8; ++ks) {
                float v1 = row[ks * 8 + u];
                float v2 = row[ks * 8 + 4 + u];
                float h1 = __uint_as_float(f2tf32(v1));
                float h2 = __uint_as_float(f2tf32(v2));
                float l1 = __uint_as_float(f2tf32(v1 - h1));
                float l2 = __uint_as_float(f2tf32(v2 - h2));
                Xa[ks * 260 + n * 4 + u] = make_float4(h1, h2, l1, l2);
            }
        } else {
            #pragma unroll
            for (int ks = 0; ks < 8; ++ks)
                Xa[ks * 260 + n * 4 + u] = make_float4(0.f, 0.f, 0.f, 0.f);
        }
    }
    __syncthreads();

    int warp = tid >> 5;
    int lane = tid & 31;
    int m0 = (warp >> 2) * 32;
    int n0 = (warp & 3) * 32;
    int r  = lane >> 2;
    int ac = lane & 3;

    float c[2][4][4];
    #pragma unroll
    for (int t = 0; t < 2; ++t)
        #pragma unroll
        for (int j = 0; j < 4; ++j)
            #pragma unroll
            for (int q = 0; q < 4; ++q) c[t][j][q] = 0.f;

    int ra = m0 + r;
    #pragma unroll
    for (int ks = 0; ks < 8; ++ks) {
        float4 a0 = Xa[ks * 260 + (ra)      * 4 + ac];
        float4 a1 = Xa[ks * 260 + (ra + 8)  * 4 + ac];
        float4 a2 = Xa[ks * 260 + (ra + 16) * 4 + ac];
        float4 a3 = Xa[ks * 260 + (ra + 24) * 4 + ac];
        unsigned ahi[2][4], alo[2][4];
        ahi[0][0] = __float_as_uint(a0.x); ahi[0][1] = __float_as_uint(a1.x);
        ahi[0][2] = __float_as_uint(a0.y); ahi[0][3] = __float_as_uint(a1.y);
        alo[0][0] = __float_as_uint(a0.z); alo[0][1] = __float_as_uint(a1.z);
        alo[0][2] = __float_as_uint(a0.w); alo[0][3] = __float_as_uint(a1.w);
        ahi[1][0] = __float_as_uint(a2.x); ahi[1][1] = __float_as_uint(a3.x);
        ahi[1][2] = __float_as_uint(a2.y); ahi[1][3] = __float_as_uint(a3.y);
        alo[1][0] = __float_as_uint(a2.z); alo[1][1] = __float_as_uint(a3.z);
        alo[1][2] = __float_as_uint(a2.w); alo[1][3] = __float_as_uint(a3.w);
        #pragma unroll
        for (int j = 0; j < 4; ++j) {
            int n = n0 + j * 8 + r;
            float4 b = __ldg(&g_Wp[ks * 512 + n * 4 + ac]);
            unsigned bh0 = __float_as_uint(b.x), bh1 = __float_as_uint(b.y);
            unsigned bl0 = __float_as_uint(b.z), bl1 = __float_as_uint(b.w);
            #pragma unroll
            for (int t = 0; t < 2; ++t) {
                asm("mma.sync.aligned.m16n8k8.row.col.f32.tf32.tf32.f32 "
                    "{%0,%1,%2,%3}, {%4,%5,%6,%7}, {%8,%9}, {%0,%1,%2,%3};"
                    : "+f"(c[t][j][0]), "+f"(c[t][j][1]), "+f"(c[t][j][2]), "+f"(c[t][j][3])
                    : "r"(ahi[t][0]), "r"(ahi[t][1]), "r"(ahi[t][2]), "r"(ahi[t][3]),
                      "r"(bh0), "r"(bh1));
                asm("mma.sync.aligned.m16n8k8.row.col.f32.tf32.tf32.f32 "
                    "{%0,%1,%2,%3}, {%4,%5,%6,%7}, {%8,%9}, {%0,%1,%2,%3};"
                    : "+f"(c[t][j][0]), "+f"(c[t][j][1]), "+f"(c[t][j][2]), "+f"(c[t][j][3])
                    : "r"(ahi[t][0]), "r"(ahi[t][1]), "r"(ahi[t][2]), "r"(ahi[t][3]),
                      "r"(bl0), "r"(bl1));
                asm("mma.sync.aligned.m16n8k8.row.col.f32.tf32.tf32.f32 "
                    "{%0,%1,%2,%3}, {%4,%5,%6,%7}, {%8,%9}, {%0,%1,%2,%3};"
                    : "+f"(c[t][j][0]), "+f"(c[t][j][1]), "+f"(c[t][j][2]), "+f"(c[t][j][3])
                    : "r"(alo[t][0]), "r"(alo[t][1]), "r"(alo[t][2]), "r"(alo[t][3]),
                      "r"(bh0), "r"(bh1));
            }
        }
    }

    if (n0 < 64) {
        #pragma unroll
        for (int t = 0; t < 2; ++t) {
            int nodeA = nbase + m0 + 16 * t + r;
            int nodeB = nodeA + 8;
            #pragma unroll
            for (int j = 0; j < 4; ++j) {
                int cp = (n0 + j * 8 + 2 * ac) >> 1;
                if (nodeA < NNODES)
                    g_xrh[nodeA * 32 + cp] = __floats2half2_rn(c[t][j][0], c[t][j][1]);
                if (nodeB < NNODES)
                    g_xrh[nodeB * 32 + cp] = __floats2half2_rn(c[t][j][2], c[t][j][3]);
            }
        }
    } else {
        int col0 = n0 - 64;
        #pragma unroll
        for (int t = 0; t < 2; ++t) {
            int nodeA = nbase + m0 + 16 * t + r;
            int nodeB = nodeA + 8;
            #pragma unroll
            for (int j = 0; j < 4; ++j) {
                int col = col0 + j * 8 + 2 * ac;
                if (nodeA < NNODES)
                    *(float2*)&g_root[nodeA * FDIM + col] = make_float2(c[t][j][0], c[t][j][1]);
                if (nodeB < NNODES)
                    *(float2*)&g_root[nodeB * FDIM + col] = make_float2(c[t][j][2], c[t][j][3]);
            }
        }
    }
}

// ---------------- aggregation: warp per node, half2 per lane ----------------
// MODE 0: write relu result to g_x (iter 1).
// MODE 2: fused iter-2 epilogue -> sparse projections g_xr4 / g_root4 (no g_x write).
template<int MODE>
__global__ void agg_kernel(const float* __restrict__ Wrel,
                           const float* __restrict__ Wroot)
{
    __shared__ float2 Wsel[8][32];     // only used by MODE 2
    if (MODE == 2) {
        int t = threadIdx.x;
        for (int i = t; i < 256; i += 256) {
            int rr = i >> 5, k2 = i & 31;
            const float* src = (rr < 4) ? &Wrel[c_pos[rr] * FDIM] : &Wroot[c_pos[rr - 4] * FDIM];
            Wsel[rr][k2] = make_float2(src[2 * k2], src[2 * k2 + 1]);
        }
        __syncthreads();
    }

    int gw   = (blockIdx.x * blockDim.x + threadIdx.x) >> 5;
    int lane = threadIdx.x & 31;
    if (gw >= NNODES) return;

    float2 acc = *(const float2*)&g_root[gw * FDIM + lane * 2];

    int e   = g_rowptr[gw];
    int end = e + g_cnt[gw];
    for (; e + 8 <= end; e += 8) {
        int s[8];
        #pragma unroll
        for (int q = 0; q < 8; ++q) s[q] = g_ssrc[e + q];
        __half2 h[8];
        #pragma unroll
        for (int q = 0; q < 8; ++q) h[q] = g_xrh[s[q] * 32 + lane];
        #pragma unroll
        for (int q = 0; q < 8; ++q) {
            float2 a = __half22float2(h[q]);
            acc.x += a.x; acc.y += a.y;
        }
    }
    for (; e < end; ++e) {
        float2 a = __half22float2(g_xrh[g_ssrc[e] * 32 + lane]);
        acc.x += a.x;
        acc.y += a.y;
    }
    acc.x = fmaxf(acc.x, 0.f);
    acc.y = fmaxf(acc.y, 0.f);

    if (MODE == 0) {
        *(float2*)&g_x[gw * FDIM + lane * 2] = acc;
    } else {
        float p[8];
        #pragma unroll
        for (int rr = 0; rr < 8; ++rr) {
            float2 w = Wsel[rr][lane];
            p[rr] = acc.x * w.x + acc.y * w.y;
        }
        #pragma unroll
        for (int off = 16; off; off >>= 1)
            #pragma unroll
            for (int rr = 0; rr < 8; ++rr)
                p[rr] += __shfl_xor_sync(0xffffffffu, p[rr], off);
        if (lane == 0) {
            g_xr4[gw]   = make_float4(p[0], p[1], p[2], p[3]);
            g_root4[gw] = make_float4(p[4], p[5], p[6], p[7]);
        }
    }
}

// ---------------- iter-3 aggregation + readout: thread per node ----------
__global__ void agg4_kernel(const float* __restrict__ evec, float* __restrict__ out)
{
    int n = blockIdx.x * blockDim.x + threadIdx.x;
    if (n >= NNODES) return;

    float4 acc = g_root4[n];
    int e   = g_rowptr[n];
    int end = e + g_cnt[n];
    for (; e + 4 <= end; e += 4) {
        int s0 = g_ssrc[e],     s1 = g_ssrc[e + 1];
        int s2 = g_ssrc[e + 2], s3 = g_ssrc[e + 3];
        float4 a0 = g_xr4[s0], a1 = g_xr4[s1];
        float4 a2 = g_xr4[s2], a3 = g_xr4[s3];
        acc.x += (a0.x + a1.x) + (a2.x + a3.x);
        acc.y += (a0.y + a1.y) + (a2.y + a3.y);
        acc.z += (a0.z + a1.z) + (a2.z + a3.z);
        acc.w += (a0.w + a1.w) + (a2.w + a3.w);
    }
    for (; e < end; ++e) {
        float4 a = g_xr4[g_ssrc[e]];
        acc.x += a.x; acc.y += a.y; acc.z += a.z; acc.w += a.w;
    }
    out[n] = fmaxf(acc.x, 0.f) * evec[15] + fmaxf(acc.y, 0.f) * evec[31]
           + fmaxf(acc.z, 0.f) * evec[47] + fmaxf(acc.w, 0.f) * evec[63];
}

// ---------------- launch (single stream; 9 launches) ----------------
extern "C" void kernel_launch(void* const* d_in, const int* in_sizes, int n_in,
                              void* d_out, int out_size) {
    const float* x = 0; const void* ei = 0;
    const float* Wrel = 0; const float* Wroot = 0; const float* evec = 0;
    for (int i = 0; i < n_in; ++i) {
        int sz = in_sizes[i];
        if (sz == NNODES * FDIM)      x = (const float*)d_in[i];
        else if (sz == 2 * NEDGES)    ei = d_in[i];
        else if (sz == FDIM * FDIM) { if (!Wrel) Wrel = (const float*)d_in[i];
                                      else       Wroot = (const float*)d_in[i]; }
        else if (sz == FDIM)          evec = (const float*)d_in[i];
    }
    float* out = (float*)d_out;

    const int GB = (NNODES + GM - 1) / GM;     // 782
    const int AB = (NNODES + 7) / 8;           // 6250
    const int TB = (NNODES + 255) / 256;       // 196

    prep_kernel<<<213, 256>>>(ei, Wrel, Wroot);            // W split + zero + detect
    hist_kernel<<<(NEDGES + 255) / 256, 256>>>(ei);
    scan_kernel<<<NCHUNK, 256>>>();

    mma_gemm_kernel<<<GB, 256>>>(x, 1);                    // iter-1 (profiled slot)

    scatter_kernel<<<(NEDGES + 255) / 256, 256>>>(ei);

    agg_kernel<0><<<AB, 256>>>(Wrel, Wroot);               // iter 1
    mma_gemm_kernel<<<GB, 256>>>(x, 0);                    // iter 2
    agg_kernel<2><<<AB, 256>>>(Wrel, Wroot);               // iter 2 agg + sparse proj
    agg4_kernel<<<TB, 256>>>(evec, out);                   // iter 3
}

// round 17
// speedup vs baseline: 1.6494x; 1.2295x over previous
#include <cuda_runtime.h>
#include <cuda_fp16.h>

#define NNODES 50000
#define NEDGES 800000
#define FDIM   64
#define NCHUNK 196        // ceil(NNODES/256)

// ---------------- scratch (static device globals; no runtime alloc) ----------------
__device__ __align__(16) float   g_x[NNODES * FDIM];    // post-relu features (iter1 only)
__device__ __align__(16) __half2 g_xrh[NNODES * 32];    // x @ W_rel.T in fp16 (gathered)
__device__ __align__(16) float   g_root[NNODES * FDIM]; // x @ W_root.T (agg init)
__device__ float4 g_xr4[NNODES];                        // iter-3 sparse columns (rel)
__device__ float4 g_root4[NNODES];                      // iter-3 sparse columns (root)
__device__ __align__(16) uint2 g_Wph[2048];             // fp16-packed W frags (16KB)
__device__ int g_rowptr[NNODES];                        // CSR row starts (chunk bases)
__device__ int g_cnt[NNODES];                           // per-node edge counts
__device__ int g_cursor[NNODES];
__device__ int g_ssrc[NEDGES];
__device__ int g_scan_ctr;
__device__ int g_is64;

__constant__ int c_pos[4] = {15, 31, 47, 63};

// ---------------- fused prep: W pack (blocks 0-7), zero counts (8-203), detect (204) ---
// g_Wph[ks*512 + n*4 + c] = { half2(W[n][ks*16+2c], W[n][ks*16+2c+1]),
//                             half2(W[n][ks*16+8+2c], W[n][ks*16+9+2c]) }
__global__ void prep_kernel(const void* ei_raw,
                            const float* __restrict__ Wrel,
                            const float* __restrict__ Wroot) {
    int b = blockIdx.x, t = threadIdx.x;
    if (b < 8) {
        int i = b * 256 + t;               // 0..2047
        int ks = i >> 9, n = (i >> 2) & 127, c = i & 3;
        const float* src = (n < 64) ? &Wrel[n * FDIM] : &Wroot[(n - 64) * FDIM];
        int k0 = ks * 16 + 2 * c;
        __half2 w0 = __floats2half2_rn(src[k0],     src[k0 + 1]);
        __half2 w1 = __floats2half2_rn(src[k0 + 8], src[k0 + 9]);
        uint2 v;
        v.x = *(unsigned*)&w0;
        v.y = *(unsigned*)&w1;
        g_Wph[i] = v;
    } else if (b < 204) {
        int i = (b - 8) * 256 + t;
        if (i < NNODES) g_cnt[i] = 0;
    } else {
        __shared__ int any_nonzero;
        if (t == 0) { any_nonzero = 0; g_scan_ctr = 0; }
        __syncthreads();
        const int* w = (const int*)ei_raw;
        #pragma unroll
        for (int q = 0; q < 4; ++q)
            if (w[2 * (t + q * 256) + 1] != 0) atomicOr(&any_nonzero, 1);
        __syncthreads();
        if (t == 0) g_is64 = any_nonzero ? 0 : 1;
    }
}

__device__ __forceinline__ int load_idx(const void* ei_raw, int pos, int is64) {
    if (is64) return (int)((const long long*)ei_raw)[pos];
    return ((const int*)ei_raw)[pos];
}

// ---------------- CSR build (by dst) ----------------
__global__ void hist_kernel(const void* __restrict__ ei_raw) {
    int e = blockIdx.x * blockDim.x + threadIdx.x;
    if (e < NEDGES) {
        int d = load_idx(ei_raw, NEDGES + e, g_is64);
        if ((unsigned)d < (unsigned)NNODES) atomicAdd(&g_cnt[d], 1);
    }
}

__global__ void scan_kernel() {
    __shared__ int ps[256];
    __shared__ int base;
    int t = threadIdx.x;
    int i = blockIdx.x * 256 + t;
    int v = (i < NNODES) ? g_cnt[i] : 0;
    ps[t] = v;
    __syncthreads();
    #pragma unroll
    for (int off = 1; off < 256; off <<= 1) {
        int u = (t >= off) ? ps[t - off] : 0;
        __syncthreads();
        ps[t] += u;
        __syncthreads();
    }
    if (t == 255) base = atomicAdd(&g_scan_ctr, ps[255]);
    __syncthreads();
    int excl = base + ps[t] - v;
    if (i < NNODES) { g_rowptr[i] = excl; g_cursor[i] = excl; }
}

__global__ void scatter_kernel(const void* __restrict__ ei_raw) {
    int e = blockIdx.x * blockDim.x + threadIdx.x;
    if (e < NEDGES) {
        int is64 = g_is64;
        int d = load_idx(ei_raw, NEDGES + e, is64);
        int s = load_idx(ei_raw, e, is64);
        if ((unsigned)d < (unsigned)NNODES && (unsigned)s < (unsigned)NNODES) {
            int p = atomicAdd(&g_cursor[d], 1);
            g_ssrc[p] = s;
        }
    }
}

// ---------------- fp16 HMMA GEMM: [xr(h) | root] = x @ [W_rel | W_root].T --------------
// Block 64 nodes x 128 outputs x K=64. 8 warps, warp tile 32M x 32N.
// A: fp16 half2 pairs in smem H[node][pair], node stride 36 (load banks (4r+ac)%32
// all-distinct). B: uint2 frags from L1-hot g_Wph. 4 ksteps of m16n8k16.
#define GM 64

__global__ void __launch_bounds__(256)
mma_gemm_kernel(const float* __restrict__ xext, int first)
{
    __shared__ __half2 H[GM * 36];     // 9216 B

    const float* xin = first ? xext : g_x;
    int tid = threadIdx.x;
    int nbase = blockIdx.x * GM;

    // ---- prologue: thread (u = tid&3, n = tid>>2) handles pairs 8u..8u+7 ----
    {
        int u = tid & 3;
        int n = tid >> 2;
        int gn = nbase + n;
        uint2* H2 = (uint2*)H;
        if (gn < NNODES) {
            const float4* row = (const float4*)&xin[gn * FDIM];
            #pragma unroll
            for (int m = 0; m < 4; ++m) {
                float4 v = row[4 * u + m];
                __half2 h0 = __floats2half2_rn(v.x, v.y);
                __half2 h1 = __floats2half2_rn(v.z, v.w);
                uint2 pk;
                pk.x = *(unsigned*)&h0;
                pk.y = *(unsigned*)&h1;
                H2[n * 18 + 4 * u + m] = pk;      // pairs 8u+2m, 8u+2m+1
            }
        } else {
            #pragma unroll
            for (int m = 0; m < 4; ++m)
                H2[n * 18 + 4 * u + m] = make_uint2(0u, 0u);
        }
    }
    __syncthreads();

    int warp = tid >> 5;
    int lane = tid & 31;
    int m0 = (warp >> 2) * 32;
    int n0 = (warp & 3) * 32;
    int r  = lane >> 2;
    int ac = lane & 3;

    float c[2][4][4];
    #pragma unroll
    for (int t = 0; t < 2; ++t)
        #pragma unroll
        for (int j = 0; j < 4; ++j)
            #pragma unroll
            for (int q = 0; q < 4; ++q) c[t][j][q] = 0.f;

    const unsigned* Hu = (const unsigned*)H;
    #pragma unroll
    for (int ks = 0; ks < 4; ++ks) {
        unsigned a[2][4];
        #pragma unroll
        for (int t = 0; t < 2; ++t) {
            int rA = m0 + 16 * t + r;
            a[t][0] = Hu[rA * 36 + ks * 8 + ac];            // (row, pair ks*8+ac)
            a[t][1] = Hu[(rA + 8) * 36 + ks * 8 + ac];
            a[t][2] = Hu[rA * 36 + ks * 8 + 4 + ac];        // (row, pair +4)
            a[t][3] = Hu[(rA + 8) * 36 + ks * 8 + 4 + ac];
        }
        #pragma unroll
        for (int j = 0; j < 4; ++j) {
            int n = n0 + j * 8 + r;
            uint2 b = __ldg(&g_Wph[ks * 512 + n * 4 + ac]);
            #pragma unroll
            for (int t = 0; t < 2; ++t) {
                asm("mma.sync.aligned.m16n8k16.row.col.f32.f16.f16.f32 "
                    "{%0,%1,%2,%3}, {%4,%5,%6,%7}, {%8,%9}, {%0,%1,%2,%3};"
                    : "+f"(c[t][j][0]), "+f"(c[t][j][1]), "+f"(c[t][j][2]), "+f"(c[t][j][3])
                    : "r"(a[t][0]), "r"(a[t][1]), "r"(a[t][2]), "r"(a[t][3]),
                      "r"(b.x), "r"(b.y));
            }
        }
    }

    if (n0 < 64) {
        #pragma unroll
        for (int t = 0; t < 2; ++t) {
            int nodeA = nbase + m0 + 16 * t + r;
            int nodeB = nodeA + 8;
            #pragma unroll
            for (int j = 0; j < 4; ++j) {
                int cp = (n0 + j * 8 + 2 * ac) >> 1;
                if (nodeA < NNODES)
                    g_xrh[nodeA * 32 + cp] = __floats2half2_rn(c[t][j][0], c[t][j][1]);
                if (nodeB < NNODES)
                    g_xrh[nodeB * 32 + cp] = __floats2half2_rn(c[t][j][2], c[t][j][3]);
            }
        }
    } else {
        int col0 = n0 - 64;
        #pragma unroll
        for (int t = 0; t < 2; ++t) {
            int nodeA = nbase + m0 + 16 * t + r;
            int nodeB = nodeA + 8;
            #pragma unroll
            for (int j = 0; j < 4; ++j) {
                int col = col0 + j * 8 + 2 * ac;
                if (nodeA < NNODES)
                    *(float2*)&g_root[nodeA * FDIM + col] = make_float2(c[t][j][0], c[t][j][1]);
                if (nodeB < NNODES)
                    *(float2*)&g_root[nodeB * FDIM + col] = make_float2(c[t][j][2], c[t][j][3]);
            }
        }
    }
}

// ---------------- aggregation: warp per node, half2 per lane ----------------
// MODE 0: write relu result to g_x (iter 1).
// MODE 2: fused iter-2 epilogue -> sparse projections g_xr4 / g_root4.
template<int MODE>
__global__ void agg_kernel(const float* __restrict__ Wrel,
                           const float* __restrict__ Wroot)
{
    __shared__ float2 Wsel[8][32];
    if (MODE == 2) {
        int t = threadIdx.x;
        for (int i = t; i < 256; i += 256) {
            int rr = i >> 5, k2 = i & 31;
            const float* src = (rr < 4) ? &Wrel[c_pos[rr] * FDIM] : &Wroot[c_pos[rr - 4] * FDIM];
            Wsel[rr][k2] = make_float2(src[2 * k2], src[2 * k2 + 1]);
        }
        __syncthreads();
    }

    int gw   = (blockIdx.x * blockDim.x + threadIdx.x) >> 5;
    int lane = threadIdx.x & 31;
    if (gw >= NNODES) return;

    float2 acc = *(const float2*)&g_root[gw * FDIM + lane * 2];

    int e   = g_rowptr[gw];
    int end = e + g_cnt[gw];
    for (; e + 8 <= end; e += 8) {
        int s[8];
        #pragma unroll
        for (int q = 0; q < 8; ++q) s[q] = g_ssrc[e + q];
        __half2 h[8];
        #pragma unroll
        for (int q = 0; q < 8; ++q) h[q] = g_xrh[s[q] * 32 + lane];
        #pragma unroll
        for (int q = 0; q < 8; ++q) {
            float2 a = __half22float2(h[q]);
            acc.x += a.x; acc.y += a.y;
        }
    }
    for (; e < end; ++e) {
        float2 a = __half22float2(g_xrh[g_ssrc[e] * 32 + lane]);
        acc.x += a.x;
        acc.y += a.y;
    }
    acc.x = fmaxf(acc.x, 0.f);
    acc.y = fmaxf(acc.y, 0.f);

    if (MODE == 0) {
        *(float2*)&g_x[gw * FDIM + lane * 2] = acc;
    } else {
        float p[8];
        #pragma unroll
        for (int rr = 0; rr < 8; ++rr) {
            float2 w = Wsel[rr][lane];
            p[rr] = acc.x * w.x + acc.y * w.y;
        }
        #pragma unroll
        for (int off = 16; off; off >>= 1)
            #pragma unroll
            for (int rr = 0; rr < 8; ++rr)
                p[rr] += __shfl_xor_sync(0xffffffffu, p[rr], off);
        if (lane == 0) {
            g_xr4[gw]   = make_float4(p[0], p[1], p[2], p[3]);
            g_root4[gw] = make_float4(p[4], p[5], p[6], p[7]);
        }
    }
}

// ---------------- iter-3 aggregation + readout: thread per node ----------
__global__ void agg4_kernel(const float* __restrict__ evec, float* __restrict__ out)
{
    int n = blockIdx.x * blockDim.x + threadIdx.x;
    if (n >= NNODES) return;

    float4 acc = g_root4[n];
    int e   = g_rowptr[n];
    int end = e + g_cnt[n];
    for (; e + 4 <= end; e += 4) {
        int s0 = g_ssrc[e],     s1 = g_ssrc[e + 1];
        int s2 = g_ssrc[e + 2], s3 = g_ssrc[e + 3];
        float4 a0 = g_xr4[s0], a1 = g_xr4[s1];
        float4 a2 = g_xr4[s2], a3 = g_xr4[s3];
        acc.x += (a0.x + a1.x) + (a2.x + a3.x);
        acc.y += (a0.y + a1.y) + (a2.y + a3.y);
        acc.z += (a0.z + a1.z) + (a2.z + a3.z);
        acc.w += (a0.w + a1.w) + (a2.w + a3.w);
    }
    for (; e < end; ++e) {
        float4 a = g_xr4[g_ssrc[e]];
        acc.x += a.x; acc.y += a.y; acc.z += a.z; acc.w += a.w;
    }
    out[n] = fmaxf(acc.x, 0.f) * evec[15] + fmaxf(acc.y, 0.f) * evec[31]
           + fmaxf(acc.z, 0.f) * evec[47] + fmaxf(acc.w, 0.f) * evec[63];
}

// ---------------- launch (single stream; 9 launches) ----------------
extern "C" void kernel_launch(void* const* d_in, const int* in_sizes, int n_in,
                              void* d_out, int out_size) {
    const float* x = 0; const void* ei = 0;
    const float* Wrel = 0; const float* Wroot = 0; const float* evec = 0;
    for (int i = 0; i < n_in; ++i) {
        int sz = in_sizes[i];
        if (sz == NNODES * FDIM)      x = (const float*)d_in[i];
        else if (sz == 2 * NEDGES)    ei = d_in[i];
        else if (sz == FDIM * FDIM) { if (!Wrel) Wrel = (const float*)d_in[i];
                                      else       Wroot = (const float*)d_in[i]; }
        else if (sz == FDIM)          evec = (const float*)d_in[i];
    }
    float* out = (float*)d_out;

    const int GB = (NNODES + GM - 1) / GM;     // 782
    const int AB = (NNODES + 7) / 8;           // 6250
    const int TB = (NNODES + 255) / 256;       // 196

    prep_kernel<<<205, 256>>>(ei, Wrel, Wroot);            // W pack + zero + detect
    hist_kernel<<<(NEDGES + 255) / 256, 256>>>(ei);
    scan_kernel<<<NCHUNK, 256>>>();

    mma_gemm_kernel<<<GB, 256>>>(x, 1);                    // iter-1 (profiled slot)

    scatter_kernel<<<(NEDGES + 255) / 256, 256>>>(ei);

    agg_kernel<0><<<AB, 256>>>(Wrel, Wroot);               // iter 1
    mma_gemm_kernel<<<GB, 256>>>(x, 0);                    // iter 2
    agg_kernel<2><<<AB, 256>>>(Wrel, Wroot);               // iter 2 agg + sparse proj
    agg4_kernel<<<TB, 256>>>(evec, out);                   // iter 3
}